// round 3
// baseline (speedup 1.0000x reference)
#include <cuda_runtime.h>

#define NMAX  100000
#define NPAD  100352        // 1024 * 98, multiple of 128
#define EMAX  1600000
#define HID   64

// ---------------- scratch (device globals; no allocation) ----------------
__device__ __align__(16) float d_dis[NPAD];          // deg_inv_sqrt
__device__ __align__(16) float d_g[NPAD * HID];      // h * dis  (layer 1, reused layer 2)
__device__ __align__(16) float d_agg1[NPAD * HID];   // layer-1 aggregation
__device__ __align__(16) float d_agg2[NPAD * HID];   // layer-2 aggregation
__device__ __align__(16) float d_g3[NPAD];           // layer-3 h*dis
__device__ int d_csr[EMAX];                          // src ids grouped by dst
__device__ int d_cnt[NPAD];                          // indegree
__device__ int d_rowstart[NPAD];                     // exclusive prefix of cnt
__device__ int d_fill[NPAD];                         // fill cursors

// ---------------- preprocessing ----------------
__global__ void k_zero() {
    int i = blockIdx.x * blockDim.x + threadIdx.x;
    if (i < NPAD) { d_cnt[i] = 0; d_fill[i] = 0; }
}

// edge_index is int32 (JAX default x64-disabled downcasts int64 -> int32)
__global__ void k_count(const int* __restrict__ ei, int E, int N) {
    int e = blockIdx.x * blockDim.x + threadIdx.x;
    if (e < E) {
        unsigned d = (unsigned)ei[E + e];
        if (d < (unsigned)N) atomicAdd(&d_cnt[d], 1);
    }
}

// single block, 1024 threads; each thread owns a 98-element chunk.
__global__ __launch_bounds__(1024) void k_scan() {
    __shared__ int sums[1024];
    int t = threadIdx.x;
    int base = t * 98;
    int s = 0;
    for (int i = 0; i < 98; i++) s += d_cnt[base + i];
    sums[t] = s;
    __syncthreads();
    // Hillis-Steele inclusive scan
    for (int off = 1; off < 1024; off <<= 1) {
        int v = (t >= off) ? sums[t - off] : 0;
        __syncthreads();
        sums[t] += v;
        __syncthreads();
    }
    int run = (t == 0) ? 0 : sums[t - 1];
    for (int i = 0; i < 98; i++) {
        int c = d_cnt[base + i];
        d_rowstart[base + i] = run;
        run += c;
        d_dis[base + i] = rsqrtf(1.0f + (float)c);   // deg = 1 (self loop) + indegree
    }
}

__global__ void k_fill(const int* __restrict__ ei, int E, int N) {
    int e = blockIdx.x * blockDim.x + threadIdx.x;
    if (e < E) {
        unsigned s = (unsigned)ei[e];
        unsigned d = (unsigned)ei[E + e];
        if (d < (unsigned)N && s < (unsigned)N) {
            int pos = d_rowstart[d] + atomicAdd(&d_fill[d], 1);
            d_csr[pos] = (int)s;
        }
    }
}

// ---------------- GEMM: H = A(NxK) @ W(Kx64); epilogue g = H*dis, agg = H*dis^2 ----------------
// tile 128 rows x 64 cols, 128 threads, each thread 8 rows x 8 cols.
template <int K, bool RELU, int LAYER>
__global__ __launch_bounds__(128)
void k_gemm(const float* __restrict__ Ain, const float* __restrict__ W,
            const float* __restrict__ bias, int N) {
    const float* __restrict__ A = (LAYER == 1) ? Ain : (const float*)d_agg1;
    float* __restrict__ g   = d_g;
    float* __restrict__ agg = (LAYER == 1) ? d_agg1 : d_agg2;

    __shared__ float As[128][33];
    __shared__ float Ws[32][64];
    __shared__ float bs[64];

    const int t = threadIdx.x;
    const int rowBase = blockIdx.x * 128;
    const int rg = t >> 3;          // 0..15 -> 8-row group
    const int cg = t & 7;           // 0..7  -> 8-col group

    float acc[8][8];
#pragma unroll
    for (int i = 0; i < 8; i++)
#pragma unroll
        for (int j = 0; j < 8; j++) acc[i][j] = 0.f;

    if (RELU) { if (t < K) bs[t] = bias[t]; }
    __syncthreads();

    for (int kc = 0; kc < K; kc += 32) {
        {
            int row = rowBase + t;
#pragma unroll
            for (int j = 0; j < 8; j++) {
                float4 v = make_float4(0.f, 0.f, 0.f, 0.f);
                if (row < N)
                    v = *(const float4*)&A[(size_t)row * K + kc + j * 4];
                if (RELU) {
                    v.x = fmaxf(v.x + bs[kc + j * 4 + 0], 0.f);
                    v.y = fmaxf(v.y + bs[kc + j * 4 + 1], 0.f);
                    v.z = fmaxf(v.z + bs[kc + j * 4 + 2], 0.f);
                    v.w = fmaxf(v.w + bs[kc + j * 4 + 3], 0.f);
                }
                As[t][j * 4 + 0] = v.x;
                As[t][j * 4 + 1] = v.y;
                As[t][j * 4 + 2] = v.z;
                As[t][j * 4 + 3] = v.w;
            }
        }
#pragma unroll
        for (int j = 0; j < 4; j++) {
            int lin = j * 128 + t;        // 0..511
            int kk = lin >> 4;            // 0..31
            int cc = (lin & 15) * 4;      // 0..60
            *(float4*)&Ws[kk][cc] = *(const float4*)&W[(size_t)(kc + kk) * 64 + cc];
        }
        __syncthreads();

#pragma unroll
        for (int k = 0; k < 32; k++) {
            float a[8];
#pragma unroll
            for (int i = 0; i < 8; i++) a[i] = As[rg * 8 + i][k];
            float4 w0 = *(const float4*)&Ws[k][cg * 8];
            float4 w1 = *(const float4*)&Ws[k][cg * 8 + 4];
#pragma unroll
            for (int i = 0; i < 8; i++) {
                acc[i][0] += a[i] * w0.x;
                acc[i][1] += a[i] * w0.y;
                acc[i][2] += a[i] * w0.z;
                acc[i][3] += a[i] * w0.w;
                acc[i][4] += a[i] * w1.x;
                acc[i][5] += a[i] * w1.y;
                acc[i][6] += a[i] * w1.z;
                acc[i][7] += a[i] * w1.w;
            }
        }
        __syncthreads();
    }

    // epilogue: g = h*dis, agg init (self-loop term) = h*dis^2
#pragma unroll
    for (int i = 0; i < 8; i++) {
        int row = rowBase + rg * 8 + i;
        float di = d_dis[row];
        float4 g0, g1, a0, a1;
        g0.x = acc[i][0] * di; g0.y = acc[i][1] * di; g0.z = acc[i][2] * di; g0.w = acc[i][3] * di;
        g1.x = acc[i][4] * di; g1.y = acc[i][5] * di; g1.z = acc[i][6] * di; g1.w = acc[i][7] * di;
        a0.x = g0.x * di; a0.y = g0.y * di; a0.z = g0.z * di; a0.w = g0.w * di;
        a1.x = g1.x * di; a1.y = g1.y * di; a1.z = g1.z * di; a1.w = g1.w * di;
        *(float4*)&g[(size_t)row * 64 + cg * 8]       = g0;
        *(float4*)&g[(size_t)row * 64 + cg * 8 + 4]   = g1;
        *(float4*)&agg[(size_t)row * 64 + cg * 8]     = a0;
        *(float4*)&agg[(size_t)row * 64 + cg * 8 + 4] = a1;
    }
}

// ---------------- gather: agg[n] += dis[n] * sum_{s in csr[n]} g[s]   (16 lanes/node) ----------------
template <int LAYER>
__global__ void k_gather(int N) {
    float* __restrict__ agg = (LAYER == 1) ? d_agg1 : d_agg2;
    int idx = blockIdx.x * blockDim.x + threadIdx.x;
    int node = idx >> 4;
    if (node >= N) return;
    int c = idx & 15;
    int beg = d_rowstart[node];
    int end = beg + d_cnt[node];
    float4 acc = make_float4(0.f, 0.f, 0.f, 0.f);
    for (int e = beg; e < end; e++) {
        int s = d_csr[e];                                  // broadcast across 16 lanes
        float4 v = *(const float4*)&d_g[(size_t)s * 64 + c * 4];
        acc.x += v.x; acc.y += v.y; acc.z += v.z; acc.w += v.w;
    }
    float w = d_dis[node];
    float4 cur = *(const float4*)&agg[(size_t)node * 64 + c * 4];
    cur.x += acc.x * w; cur.y += acc.y * w; cur.z += acc.z * w; cur.w += acc.w * w;
    *(float4*)&agg[(size_t)node * 64 + c * 4] = cur;
}

// ---------------- layer 3: dot-64 per node + self term ----------------
__global__ void k_layer3(const float* __restrict__ W3, const float* __restrict__ b2,
                         const float* __restrict__ b3, float* __restrict__ out, int N) {
    __shared__ float w[64];
    __shared__ float bb[64];
    if (threadIdx.x < 64) {
        w[threadIdx.x] = W3[threadIdx.x];
        bb[threadIdx.x] = b2[threadIdx.x];
    }
    __syncthreads();
    int i = blockIdx.x * blockDim.x + threadIdx.x;
    if (i >= N) return;
    const float4* a = (const float4*)(d_agg2 + (size_t)i * 64);
    float s = 0.f;
#pragma unroll
    for (int j = 0; j < 16; j++) {
        float4 v = a[j];
        s += fmaxf(v.x + bb[j * 4 + 0], 0.f) * w[j * 4 + 0];
        s += fmaxf(v.y + bb[j * 4 + 1], 0.f) * w[j * 4 + 1];
        s += fmaxf(v.z + bb[j * 4 + 2], 0.f) * w[j * 4 + 2];
        s += fmaxf(v.w + bb[j * 4 + 3], 0.f) * w[j * 4 + 3];
    }
    float di = d_dis[i];
    d_g3[i] = s * di;
    out[i]  = s * di * di + b3[0];
}

__global__ void k_gather_out(float* __restrict__ out, int N) {
    int i = blockIdx.x * blockDim.x + threadIdx.x;
    if (i >= N) return;
    int beg = d_rowstart[i];
    int end = beg + d_cnt[i];
    float s = 0.f;
    for (int e = beg; e < end; e++) s += d_g3[d_csr[e]];
    out[i] += s * d_dis[i];
}

// ---------------- launch ----------------
extern "C" void kernel_launch(void* const* d_in, const int* in_sizes, int n_in,
                              void* d_out, int out_size) {
    const float* x  = (const float*)d_in[0];
    const int*   ei = (const int*)d_in[1];        // int32! (JAX x64 disabled)
    const float* W1 = (const float*)d_in[2];
    const float* b1 = (const float*)d_in[3];
    const float* W2 = (const float*)d_in[4];
    const float* b2 = (const float*)d_in[5];
    const float* W3 = (const float*)d_in[6];
    const float* b3 = (const float*)d_in[7];
    float* out = (float*)d_out;

    int N = in_sizes[0] / 128;
    int E = in_sizes[1] / 2;

    // preprocessing: CSR by dst + norms
    k_zero<<<(NPAD + 255) / 256, 256>>>();
    k_count<<<(E + 255) / 256, 256>>>(ei, E, N);
    k_scan<<<1, 1024>>>();
    k_fill<<<(E + 255) / 256, 256>>>(ei, E, N);

    const int gblocks = NPAD / 128;
    const int gather_blocks = (N * 16 + 255) / 256;

    // layer 1
    k_gemm<128, false, 1><<<gblocks, 128>>>(x, W1, nullptr, N);
    k_gather<1><<<gather_blocks, 256>>>(N);
    // layer 2 (bias+relu fused into A load)
    k_gemm<64, true, 2><<<gblocks, 128>>>(nullptr, W2, b1, NPAD);
    k_gather<2><<<gather_blocks, 256>>>(N);
    // layer 3
    k_layer3<<<(N + 127) / 128, 128>>>(W3, b2, b3, out, N);
    k_gather_out<<<(N + 255) / 256, 256>>>(out, N);
}

// round 4
// speedup vs baseline: 1.0894x; 1.0894x over previous
#include <cuda_runtime.h>
#include <cuda_fp16.h>

#define NMAX  100000
#define NPAD  100352        // 1024 * 98, multiple of 128
#define EMAX  1600000
#define HID   64

// ---------------- scratch (device globals; no allocation) ----------------
__device__ __align__(16) float  d_dis[NPAD];          // deg_inv_sqrt
__device__ __align__(16) __half d_gh[NPAD * HID];     // h (raw, fp16) for gather layers
__device__ __align__(16) float  d_agg1[NPAD * HID];   // layer-1 aggregation (fp32)
__device__ __align__(16) float  d_agg2[NPAD * HID];   // layer-2 aggregation (fp32)
__device__ __align__(16) float  d_g3[NPAD];           // layer-3 h*dis
__device__ int d_csr[EMAX];                           // src ids grouped by dst
__device__ int d_cnt[NPAD];                           // indegree (consumed as cursor by fill)
__device__ int d_rowstart[NPAD + 1];                  // exclusive prefix of cnt

// ---------------- preprocessing ----------------
__global__ void k_zero() {
    int i = blockIdx.x * blockDim.x + threadIdx.x;
    if (i < NPAD) d_cnt[i] = 0;
}

// edge_index is int32 (JAX x64 disabled)
__global__ void k_count(const int* __restrict__ ei, int E, int N) {
    int e = blockIdx.x * blockDim.x + threadIdx.x;
    if (e < E) {
        unsigned d = (unsigned)ei[E + e];
        if (d < (unsigned)N) atomicAdd(&d_cnt[d], 1);
    }
}

// single block, 1024 threads; each thread owns a 98-element chunk.
__global__ __launch_bounds__(1024) void k_scan() {
    __shared__ int sums[1024];
    int t = threadIdx.x;
    int base = t * 98;
    int s = 0;
    for (int i = 0; i < 98; i++) s += d_cnt[base + i];
    sums[t] = s;
    __syncthreads();
    for (int off = 1; off < 1024; off <<= 1) {
        int v = (t >= off) ? sums[t - off] : 0;
        __syncthreads();
        sums[t] += v;
        __syncthreads();
    }
    int run = (t == 0) ? 0 : sums[t - 1];
    for (int i = 0; i < 98; i++) {
        int c = d_cnt[base + i];
        d_rowstart[base + i] = run;
        run += c;
        d_dis[base + i] = rsqrtf(1.0f + (float)c);   // deg = 1 (self loop) + indegree
    }
    if (t == 1023) d_rowstart[NPAD] = run;
}

// backward fill: cursor = indegree count, decremented to 0 (order irrelevant for sums)
__global__ void k_fill(const int* __restrict__ ei, int E, int N) {
    int e = blockIdx.x * blockDim.x + threadIdx.x;
    if (e < E) {
        unsigned s = (unsigned)ei[e];
        unsigned d = (unsigned)ei[E + e];
        if (d < (unsigned)N && s < (unsigned)N) {
            int pos = d_rowstart[d] + atomicSub(&d_cnt[d], 1) - 1;
            d_csr[pos] = (int)s;
        }
    }
}

// ---------------- GEMM: H = A(NxK) @ W(Kx64); epilogue writes h as fp16 ----------------
// tile 128 rows x 64 cols, 128 threads, each thread 8 rows x 8 cols.
template <int K, bool RELU, int LAYER>
__global__ __launch_bounds__(128)
void k_gemm(const float* __restrict__ Ain, const float* __restrict__ W,
            const float* __restrict__ bias, int N) {
    const float* __restrict__ A = (LAYER == 1) ? Ain : (const float*)d_agg1;

    __shared__ float As[128][33];
    __shared__ float Ws[32][64];
    __shared__ float bs[64];

    const int t = threadIdx.x;
    const int rowBase = blockIdx.x * 128;
    const int rg = t >> 3;          // 0..15 -> 8-row group
    const int cg = t & 7;           // 0..7  -> 8-col group

    float acc[8][8];
#pragma unroll
    for (int i = 0; i < 8; i++)
#pragma unroll
        for (int j = 0; j < 8; j++) acc[i][j] = 0.f;

    if (RELU) { if (t < K) bs[t] = bias[t]; }
    __syncthreads();

    for (int kc = 0; kc < K; kc += 32) {
        {
            int row = rowBase + t;
#pragma unroll
            for (int j = 0; j < 8; j++) {
                float4 v = make_float4(0.f, 0.f, 0.f, 0.f);
                if (row < N)
                    v = *(const float4*)&A[(size_t)row * K + kc + j * 4];
                if (RELU) {
                    v.x = fmaxf(v.x + bs[kc + j * 4 + 0], 0.f);
                    v.y = fmaxf(v.y + bs[kc + j * 4 + 1], 0.f);
                    v.z = fmaxf(v.z + bs[kc + j * 4 + 2], 0.f);
                    v.w = fmaxf(v.w + bs[kc + j * 4 + 3], 0.f);
                }
                As[t][j * 4 + 0] = v.x;
                As[t][j * 4 + 1] = v.y;
                As[t][j * 4 + 2] = v.z;
                As[t][j * 4 + 3] = v.w;
            }
        }
#pragma unroll
        for (int j = 0; j < 4; j++) {
            int lin = j * 128 + t;        // 0..511
            int kk = lin >> 4;            // 0..31
            int cc = (lin & 15) * 4;      // 0..60
            *(float4*)&Ws[kk][cc] = *(const float4*)&W[(size_t)(kc + kk) * 64 + cc];
        }
        __syncthreads();

#pragma unroll
        for (int k = 0; k < 32; k++) {
            float a[8];
#pragma unroll
            for (int i = 0; i < 8; i++) a[i] = As[rg * 8 + i][k];
            float4 w0 = *(const float4*)&Ws[k][cg * 8];
            float4 w1 = *(const float4*)&Ws[k][cg * 8 + 4];
#pragma unroll
            for (int i = 0; i < 8; i++) {
                acc[i][0] += a[i] * w0.x;
                acc[i][1] += a[i] * w0.y;
                acc[i][2] += a[i] * w0.z;
                acc[i][3] += a[i] * w0.w;
                acc[i][4] += a[i] * w1.x;
                acc[i][5] += a[i] * w1.y;
                acc[i][6] += a[i] * w1.z;
                acc[i][7] += a[i] * w1.w;
            }
        }
        __syncthreads();
    }

    // epilogue: store h as fp16 (no dis here -> GEMM1 independent of preprocessing)
#pragma unroll
    for (int i = 0; i < 8; i++) {
        int row = rowBase + rg * 8 + i;
        __half2 h0 = __floats2half2_rn(acc[i][0], acc[i][1]);
        __half2 h1 = __floats2half2_rn(acc[i][2], acc[i][3]);
        __half2 h2 = __floats2half2_rn(acc[i][4], acc[i][5]);
        __half2 h3 = __floats2half2_rn(acc[i][6], acc[i][7]);
        uint4 u;
        u.x = *(unsigned*)&h0; u.y = *(unsigned*)&h1;
        u.z = *(unsigned*)&h2; u.w = *(unsigned*)&h3;
        *(uint4*)&d_gh[(size_t)row * 64 + cg * 8] = u;
    }
}

// ---------------- gather: agg[n] = dis[n] * (sum_s h[s]*dis[s] + h[n]*dis[n]) ----------------
// 16 lanes/node; each lane owns 4 halves (uint2 = 8B) -> one 128B line per edge.
template <int LAYER>
__global__ void k_gather(int N) {
    float* __restrict__ agg = (LAYER == 1) ? d_agg1 : d_agg2;
    int idx = blockIdx.x * blockDim.x + threadIdx.x;
    int node = idx >> 4;
    if (node >= N) return;
    int c = (idx & 15) * 4;                   // half index within row
    int beg = d_rowstart[node];
    int end = d_rowstart[node + 1];
    float dn = d_dis[node];
    float4 acc;
    {
        uint2 u = *(const uint2*)&d_gh[(size_t)node * 64 + c];
        float2 f0 = __half22float2(*(__half2*)&u.x);
        float2 f1 = __half22float2(*(__half2*)&u.y);
        acc = make_float4(f0.x * dn, f0.y * dn, f1.x * dn, f1.y * dn);
    }
    for (int e = beg; e < end; e++) {
        int s = d_csr[e];                     // broadcast across the 16 lanes
        float ds = d_dis[s];
        uint2 u = *(const uint2*)&d_gh[(size_t)s * 64 + c];
        float2 f0 = __half22float2(*(__half2*)&u.x);
        float2 f1 = __half22float2(*(__half2*)&u.y);
        acc.x += f0.x * ds; acc.y += f0.y * ds;
        acc.z += f1.x * ds; acc.w += f1.y * ds;
    }
    *(float4*)&agg[(size_t)node * 64 + c] =
        make_float4(acc.x * dn, acc.y * dn, acc.z * dn, acc.w * dn);
}

// ---------------- layer 3: dot-64 per node + self term ----------------
__global__ void k_layer3(const float* __restrict__ W3, const float* __restrict__ b2,
                         const float* __restrict__ b3, float* __restrict__ out, int N) {
    __shared__ float w[64];
    __shared__ float bb[64];
    if (threadIdx.x < 64) {
        w[threadIdx.x] = W3[threadIdx.x];
        bb[threadIdx.x] = b2[threadIdx.x];
    }
    __syncthreads();
    int i = blockIdx.x * blockDim.x + threadIdx.x;
    if (i >= N) return;
    const float4* a = (const float4*)(d_agg2 + (size_t)i * 64);
    float s = 0.f;
#pragma unroll
    for (int j = 0; j < 16; j++) {
        float4 v = a[j];
        s += fmaxf(v.x + bb[j * 4 + 0], 0.f) * w[j * 4 + 0];
        s += fmaxf(v.y + bb[j * 4 + 1], 0.f) * w[j * 4 + 1];
        s += fmaxf(v.z + bb[j * 4 + 2], 0.f) * w[j * 4 + 2];
        s += fmaxf(v.w + bb[j * 4 + 3], 0.f) * w[j * 4 + 3];
    }
    float di = d_dis[i];
    d_g3[i] = s * di;                 // premultiplied by dis[src]
    out[i]  = s * di * di + b3[0];
}

__global__ void k_gather_out(float* __restrict__ out, int N) {
    int i = blockIdx.x * blockDim.x + threadIdx.x;
    if (i >= N) return;
    int beg = d_rowstart[i];
    int end = d_rowstart[i + 1];
    float s = 0.f;
    for (int e = beg; e < end; e++) s += d_g3[d_csr[e]];
    out[i] += s * d_dis[i];
}

// ---------------- launch ----------------
extern "C" void kernel_launch(void* const* d_in, const int* in_sizes, int n_in,
                              void* d_out, int out_size) {
    const float* x  = (const float*)d_in[0];
    const int*   ei = (const int*)d_in[1];        // int32 (JAX x64 disabled)
    const float* W1 = (const float*)d_in[2];
    const float* b1 = (const float*)d_in[3];
    const float* W2 = (const float*)d_in[4];
    const float* b2 = (const float*)d_in[5];
    const float* W3 = (const float*)d_in[6];
    const float* b3 = (const float*)d_in[7];
    float* out = (float*)d_out;

    int N = in_sizes[0] / 128;
    int E = in_sizes[1] / 2;

    // one-time infra (created on the first, non-captured, correctness call)
    static cudaStream_t s2 = nullptr;
    static cudaEvent_t ev_fork = nullptr, ev_gemm = nullptr;
    if (!s2) {
        cudaStreamCreateWithFlags(&s2, cudaStreamNonBlocking);
        cudaEventCreateWithFlags(&ev_fork, cudaEventDisableTiming);
        cudaEventCreateWithFlags(&ev_gemm, cudaEventDisableTiming);
    }

    const int gblocks = NPAD / 128;
    const int gather_blocks = (N * 16 + 255) / 256;

    // fork: GEMM1 (independent of graph preprocessing) on s2
    cudaEventRecord(ev_fork, 0);
    cudaStreamWaitEvent(s2, ev_fork, 0);
    k_gemm<128, false, 1><<<gblocks, 128, 0, s2>>>(x, W1, nullptr, N);
    cudaEventRecord(ev_gemm, s2);

    // preprocessing on the main stream: CSR by dst + norms
    k_zero<<<(NPAD + 255) / 256, 256>>>();
    k_count<<<(E + 255) / 256, 256>>>(ei, E, N);
    k_scan<<<1, 1024>>>();
    k_fill<<<(E + 255) / 256, 256>>>(ei, E, N);

    // join, then layer 1 aggregation
    cudaStreamWaitEvent(0, ev_gemm, 0);
    k_gather<1><<<gather_blocks, 256>>>(N);

    // layer 2 (bias+relu fused into A load)
    k_gemm<64, true, 2><<<gblocks, 128>>>(nullptr, W2, b1, NPAD);
    k_gather<2><<<gather_blocks, 256>>>(N);

    // layer 3
    k_layer3<<<(N + 127) / 128, 128>>>(W3, b2, b3, out, N);
    k_gather_out<<<(N + 255) / 256, 256>>>(out, N);
}

// round 5
// speedup vs baseline: 1.7514x; 1.6077x over previous
#include <cuda_runtime.h>
#include <cuda_fp16.h>

#define NMAX  100000
#define NPAD  100352        // 1024 * 98, multiple of 128
#define NBLK  98            // NPAD / 1024
#define EMAX  1600000
#define HID   64

// ---------------- scratch (device globals; no allocation) ----------------
__device__ __align__(16) float  d_dis[NPAD];          // deg_inv_sqrt
__device__ __align__(16) __half d_gh[NPAD * HID];     // h (raw, fp16) for gather layers
__device__ __align__(16) float  d_agg1[NPAD * HID];   // layer-1 aggregation (fp32)
__device__ __align__(16) float  d_agg2[NPAD * HID];   // layer-2 aggregation (fp32)
__device__ __align__(16) float  d_g3[NPAD];           // layer-3 h*dis
__device__ int d_csr[EMAX];                           // src ids grouped by dst
__device__ int d_cnt[NPAD];                           // indegree (zero-init; fill drains to 0)
__device__ int d_rowstart[NPAD + 1];                  // exclusive prefix of cnt
__device__ int d_bsum[NBLK];                          // per-block sums
__device__ int d_boff[NBLK];                          // per-block exclusive offsets

// ---------------- preprocessing ----------------
// edge_index is int32 (JAX x64 disabled)
__global__ void k_count(const int* __restrict__ ei, int E, int N) {
    int e = blockIdx.x * blockDim.x + threadIdx.x;
    if (e < E) {
        unsigned d = (unsigned)ei[E + e];
        if (d < (unsigned)N) atomicAdd(&d_cnt[d], 1);
    }
}

// phase 1: per-block reduce + fused dis
__global__ __launch_bounds__(1024) void k_scan1() {
    int b = blockIdx.x, t = threadIdx.x;
    int i = b * 1024 + t;
    int c = d_cnt[i];
    d_dis[i] = rsqrtf(1.0f + (float)c);
    __shared__ int sh[32];
    int v = c;
#pragma unroll
    for (int o = 16; o; o >>= 1) v += __shfl_down_sync(~0u, v, o);
    if ((t & 31) == 0) sh[t >> 5] = v;
    __syncthreads();
    if (t < 32) {
        int w = sh[t];
#pragma unroll
        for (int o = 16; o; o >>= 1) w += __shfl_down_sync(~0u, w, o);
        if (t == 0) d_bsum[b] = w;
    }
}

// phase 2: scan the 98 block sums (one tiny block)
__global__ void k_scan2() {
    __shared__ int sh[128];
    int t = threadIdx.x;
    int v = (t < NBLK) ? d_bsum[t] : 0;
    sh[t] = v;
    __syncthreads();
    for (int o = 1; o < 128; o <<= 1) {
        int u = (t >= o) ? sh[t - o] : 0;
        __syncthreads();
        sh[t] += u;
        __syncthreads();
    }
    if (t < NBLK) d_boff[t] = sh[t] - v;          // exclusive
    if (t == NBLK - 1) d_rowstart[NPAD] = sh[t];
}

// phase 3: in-block exclusive scan + block offset
__global__ __launch_bounds__(1024) void k_scan3() {
    __shared__ int sh[1024];
    int b = blockIdx.x, t = threadIdx.x;
    int c = d_cnt[b * 1024 + t];
    sh[t] = c;
    __syncthreads();
    for (int o = 1; o < 1024; o <<= 1) {
        int u = (t >= o) ? sh[t - o] : 0;
        __syncthreads();
        sh[t] += u;
        __syncthreads();
    }
    d_rowstart[b * 1024 + t] = d_boff[b] + sh[t] - c;
}

// backward fill: cursor = indegree count, decremented to 0 (restores d_cnt == 0 invariant)
__global__ void k_fill(const int* __restrict__ ei, int E, int N) {
    int e = blockIdx.x * blockDim.x + threadIdx.x;
    if (e < E) {
        int s = ei[e];
        unsigned d = (unsigned)ei[E + e];
        if (d < (unsigned)N) {
            int pos = d_rowstart[d] + atomicSub(&d_cnt[d], 1) - 1;
            d_csr[pos] = s;
        }
    }
}

// ---------------- GEMM: H = A(NxK) @ W(Kx64); epilogue writes h as fp16 ----------------
// tile 128 rows x 64 cols, 128 threads, each thread 8 rows x 8 cols.
template <int K, bool RELU, int LAYER>
__global__ __launch_bounds__(128)
void k_gemm(const float* __restrict__ Ain, const float* __restrict__ W,
            const float* __restrict__ bias, int N) {
    const float* __restrict__ A = (LAYER == 1) ? Ain : (const float*)d_agg1;

    __shared__ float As[128][33];
    __shared__ float Ws[32][64];
    __shared__ float bs[64];

    const int t = threadIdx.x;
    const int rowBase = blockIdx.x * 128;
    const int rg = t >> 3;          // 0..15 -> 8-row group
    const int cg = t & 7;           // 0..7  -> 8-col group

    float acc[8][8];
#pragma unroll
    for (int i = 0; i < 8; i++)
#pragma unroll
        for (int j = 0; j < 8; j++) acc[i][j] = 0.f;

    if (RELU) { if (t < K) bs[t] = bias[t]; }
    __syncthreads();

    for (int kc = 0; kc < K; kc += 32) {
        {
            int row = rowBase + t;
#pragma unroll
            for (int j = 0; j < 8; j++) {
                float4 v = make_float4(0.f, 0.f, 0.f, 0.f);
                if (row < N)
                    v = *(const float4*)&A[(size_t)row * K + kc + j * 4];
                if (RELU) {
                    v.x = fmaxf(v.x + bs[kc + j * 4 + 0], 0.f);
                    v.y = fmaxf(v.y + bs[kc + j * 4 + 1], 0.f);
                    v.z = fmaxf(v.z + bs[kc + j * 4 + 2], 0.f);
                    v.w = fmaxf(v.w + bs[kc + j * 4 + 3], 0.f);
                }
                As[t][j * 4 + 0] = v.x;
                As[t][j * 4 + 1] = v.y;
                As[t][j * 4 + 2] = v.z;
                As[t][j * 4 + 3] = v.w;
            }
        }
#pragma unroll
        for (int j = 0; j < 4; j++) {
            int lin = j * 128 + t;        // 0..511
            int kk = lin >> 4;            // 0..31
            int cc = (lin & 15) * 4;      // 0..60
            *(float4*)&Ws[kk][cc] = *(const float4*)&W[(size_t)(kc + kk) * 64 + cc];
        }
        __syncthreads();

#pragma unroll
        for (int k = 0; k < 32; k++) {
            float a[8];
#pragma unroll
            for (int i = 0; i < 8; i++) a[i] = As[rg * 8 + i][k];
            float4 w0 = *(const float4*)&Ws[k][cg * 8];
            float4 w1 = *(const float4*)&Ws[k][cg * 8 + 4];
#pragma unroll
            for (int i = 0; i < 8; i++) {
                acc[i][0] += a[i] * w0.x;
                acc[i][1] += a[i] * w0.y;
                acc[i][2] += a[i] * w0.z;
                acc[i][3] += a[i] * w0.w;
                acc[i][4] += a[i] * w1.x;
                acc[i][5] += a[i] * w1.y;
                acc[i][6] += a[i] * w1.z;
                acc[i][7] += a[i] * w1.w;
            }
        }
        __syncthreads();
    }

    // epilogue: store h as fp16 (no dis -> GEMM1 independent of preprocessing)
#pragma unroll
    for (int i = 0; i < 8; i++) {
        int row = rowBase + rg * 8 + i;
        __half2 h0 = __floats2half2_rn(acc[i][0], acc[i][1]);
        __half2 h1 = __floats2half2_rn(acc[i][2], acc[i][3]);
        __half2 h2 = __floats2half2_rn(acc[i][4], acc[i][5]);
        __half2 h3 = __floats2half2_rn(acc[i][6], acc[i][7]);
        uint4 u;
        u.x = *(unsigned*)&h0; u.y = *(unsigned*)&h1;
        u.z = *(unsigned*)&h2; u.w = *(unsigned*)&h3;
        *(uint4*)&d_gh[(size_t)row * 64 + cg * 8] = u;
    }
}

// ---------------- gather: agg[n] = dis[n] * (sum_s h[s]*dis[s] + h[n]*dis[n]) ----------------
// 16 lanes/node; each lane owns 4 halves (uint2 = 8B) -> one 128B line per edge.
template <int LAYER>
__global__ void k_gather(int N) {
    float* __restrict__ agg = (LAYER == 1) ? d_agg1 : d_agg2;
    int idx = blockIdx.x * blockDim.x + threadIdx.x;
    int node = idx >> 4;
    if (node >= N) return;
    int c = (idx & 15) * 4;                   // half index within row
    int beg = d_rowstart[node];
    int end = d_rowstart[node + 1];
    float dn = d_dis[node];
    float4 acc;
    {
        uint2 u = *(const uint2*)&d_gh[(size_t)node * 64 + c];
        float2 f0 = __half22float2(*(__half2*)&u.x);
        float2 f1 = __half22float2(*(__half2*)&u.y);
        acc = make_float4(f0.x * dn, f0.y * dn, f1.x * dn, f1.y * dn);
    }
    for (int e = beg; e < end; e++) {
        int s = d_csr[e];                     // broadcast across the 16 lanes
        float ds = d_dis[s];
        uint2 u = *(const uint2*)&d_gh[(size_t)s * 64 + c];
        float2 f0 = __half22float2(*(__half2*)&u.x);
        float2 f1 = __half22float2(*(__half2*)&u.y);
        acc.x += f0.x * ds; acc.y += f0.y * ds;
        acc.z += f1.x * ds; acc.w += f1.y * ds;
    }
    *(float4*)&agg[(size_t)node * 64 + c] =
        make_float4(acc.x * dn, acc.y * dn, acc.z * dn, acc.w * dn);
}

// ---------------- layer 3: dot-64 per node + self term ----------------
__global__ void k_layer3(const float* __restrict__ W3, const float* __restrict__ b2,
                         const float* __restrict__ b3, float* __restrict__ out, int N) {
    __shared__ float w[64];
    __shared__ float bb[64];
    if (threadIdx.x < 64) {
        w[threadIdx.x] = W3[threadIdx.x];
        bb[threadIdx.x] = b2[threadIdx.x];
    }
    __syncthreads();
    int i = blockIdx.x * blockDim.x + threadIdx.x;
    if (i >= N) return;
    const float4* a = (const float4*)(d_agg2 + (size_t)i * 64);
    float s = 0.f;
#pragma unroll
    for (int j = 0; j < 16; j++) {
        float4 v = a[j];
        s += fmaxf(v.x + bb[j * 4 + 0], 0.f) * w[j * 4 + 0];
        s += fmaxf(v.y + bb[j * 4 + 1], 0.f) * w[j * 4 + 1];
        s += fmaxf(v.z + bb[j * 4 + 2], 0.f) * w[j * 4 + 2];
        s += fmaxf(v.w + bb[j * 4 + 3], 0.f) * w[j * 4 + 3];
    }
    float di = d_dis[i];
    d_g3[i] = s * di;                 // premultiplied by dis[src]
    out[i]  = s * di * di + b3[0];
}

__global__ void k_gather_out(float* __restrict__ out, int N) {
    int i = blockIdx.x * blockDim.x + threadIdx.x;
    if (i >= N) return;
    int beg = d_rowstart[i];
    int end = d_rowstart[i + 1];
    float s = 0.f;
    for (int e = beg; e < end; e++) s += d_g3[d_csr[e]];
    out[i] += s * d_dis[i];
}

// ---------------- launch ----------------
extern "C" void kernel_launch(void* const* d_in, const int* in_sizes, int n_in,
                              void* d_out, int out_size) {
    const float* x  = (const float*)d_in[0];
    const int*   ei = (const int*)d_in[1];        // int32 (JAX x64 disabled)
    const float* W1 = (const float*)d_in[2];
    const float* b1 = (const float*)d_in[3];
    const float* W2 = (const float*)d_in[4];
    const float* b2 = (const float*)d_in[5];
    const float* W3 = (const float*)d_in[6];
    const float* b3 = (const float*)d_in[7];
    float* out = (float*)d_out;

    int N = in_sizes[0] / 128;
    int E = in_sizes[1] / 2;

    static cudaStream_t s2 = nullptr;
    static cudaEvent_t ev_fork = nullptr, ev_gemm = nullptr;
    if (!s2) {
        cudaStreamCreateWithFlags(&s2, cudaStreamNonBlocking);
        cudaEventCreateWithFlags(&ev_fork, cudaEventDisableTiming);
        cudaEventCreateWithFlags(&ev_gemm, cudaEventDisableTiming);
    }

    const int gblocks = NPAD / 128;
    const int gather_blocks = (N * 16 + 255) / 256;

    // fork: GEMM1 (independent of graph preprocessing) on s2
    cudaEventRecord(ev_fork, 0);
    cudaStreamWaitEvent(s2, ev_fork, 0);
    k_gemm<128, false, 1><<<gblocks, 128, 0, s2>>>(x, W1, nullptr, N);
    cudaEventRecord(ev_gemm, s2);

    // preprocessing on the main stream: CSR by dst + norms
    // (d_cnt is all-zero on entry: zero-init at load, k_fill drains it back to zero)
    k_count<<<(E + 255) / 256, 256>>>(ei, E, N);
    k_scan1<<<NBLK, 1024>>>();
    k_scan2<<<1, 128>>>();
    k_scan3<<<NBLK, 1024>>>();
    k_fill<<<(E + 255) / 256, 256>>>(ei, E, N);

    // join, then layer 1 aggregation
    cudaStreamWaitEvent(0, ev_gemm, 0);
    k_gather<1><<<gather_blocks, 256>>>(N);

    // layer 2 (bias+relu fused into A load)
    k_gemm<64, true, 2><<<gblocks, 128>>>(nullptr, W2, b1, NPAD);
    k_gather<2><<<gather_blocks, 256>>>(N);

    // layer 3
    k_layer3<<<(N + 127) / 128, 128>>>(W3, b2, b3, out, N);
    k_gather_out<<<(N + 255) / 256, 256>>>(out, N);
}

// round 6
// speedup vs baseline: 2.2308x; 1.2737x over previous
#include <cuda_runtime.h>
#include <cuda_fp16.h>
#include <mma.h>

using namespace nvcuda;

#define NMAX  100000
#define NPAD  100352        // 1024 * 98, multiple of 128
#define NBLK  98            // NPAD / 1024
#define EMAX  1600000
#define HID   64

// ---------------- scratch (device globals; no allocation) ----------------
__device__ __align__(16) float  d_dis[NPAD];          // deg_inv_sqrt
__device__ __align__(16) __half d_gh[NPAD * HID];     // h (raw, fp16) for gather layers
__device__ __align__(16) float  d_agg1[NPAD * HID];   // layer-1 aggregation (fp32)
__device__ __align__(16) float  d_g3[NPAD];           // layer-3 h*dis
__device__ int d_csr[EMAX];                           // src ids grouped by dst
__device__ int d_cnt[NPAD];                           // indegree (zero-init; fill drains to 0)
__device__ int d_rowstart[NPAD + 1];                  // exclusive prefix of cnt
__device__ int d_bsum[NBLK];
__device__ int d_boff[NBLK];

// ---------------- preprocessing ----------------
__global__ void k_count(const int* __restrict__ ei, int E, int N) {
    int e = blockIdx.x * blockDim.x + threadIdx.x;
    if (e < E) {
        unsigned d = (unsigned)ei[E + e];
        if (d < (unsigned)N) atomicAdd(&d_cnt[d], 1);
    }
}

__global__ __launch_bounds__(1024) void k_scan1() {
    int b = blockIdx.x, t = threadIdx.x;
    int i = b * 1024 + t;
    int c = d_cnt[i];
    d_dis[i] = rsqrtf(1.0f + (float)c);
    __shared__ int sh[32];
    int v = c;
#pragma unroll
    for (int o = 16; o; o >>= 1) v += __shfl_down_sync(~0u, v, o);
    if ((t & 31) == 0) sh[t >> 5] = v;
    __syncthreads();
    if (t < 32) {
        int w = sh[t];
#pragma unroll
        for (int o = 16; o; o >>= 1) w += __shfl_down_sync(~0u, w, o);
        if (t == 0) d_bsum[b] = w;
    }
}

__global__ void k_scan2() {
    __shared__ int sh[128];
    int t = threadIdx.x;
    int v = (t < NBLK) ? d_bsum[t] : 0;
    sh[t] = v;
    __syncthreads();
    for (int o = 1; o < 128; o <<= 1) {
        int u = (t >= o) ? sh[t - o] : 0;
        __syncthreads();
        sh[t] += u;
        __syncthreads();
    }
    if (t < NBLK) d_boff[t] = sh[t] - v;
    if (t == NBLK - 1) d_rowstart[NPAD] = sh[t];
}

__global__ __launch_bounds__(1024) void k_scan3() {
    __shared__ int sh[1024];
    int b = blockIdx.x, t = threadIdx.x;
    int c = d_cnt[b * 1024 + t];
    sh[t] = c;
    __syncthreads();
    for (int o = 1; o < 1024; o <<= 1) {
        int u = (t >= o) ? sh[t - o] : 0;
        __syncthreads();
        sh[t] += u;
        __syncthreads();
    }
    d_rowstart[b * 1024 + t] = d_boff[b] + sh[t] - c;
}

// backward fill: drains d_cnt back to 0 (keeps the zero-on-entry invariant)
__global__ void k_fill(const int* __restrict__ ei, int E, int N) {
    int e = blockIdx.x * blockDim.x + threadIdx.x;
    if (e < E) {
        int s = ei[e];
        unsigned d = (unsigned)ei[E + e];
        if (d < (unsigned)N) {
            int pos = d_rowstart[d] + atomicSub(&d_cnt[d], 1) - 1;
            d_csr[pos] = s;
        }
    }
}

// ---------------- tensor-core GEMM: H = A(NxK) @ W(Kx64), fp16 in / fp32 acc ----------------
// block: 256 threads (8 warps), tile 128 x 64. Warp w owns rows 16w..16w+15.
// RELU (layer 2 only, K==64): A-load applies +bias, relu. Epilogue stores h as fp16.
template <int K, bool RELU, int LAYER>
__global__ __launch_bounds__(256)
void k_gemm(const float* __restrict__ Ain, const float* __restrict__ W,
            const float* __restrict__ bias, int N) {
    const float* __restrict__ A = (LAYER == 1) ? Ain : (const float*)d_agg1;
    constexpr int KC  = 64;   // k-chunk
    constexpr int AST = 72;   // A smem stride (halfs), %8==0, conflict-free-ish
    constexpr int BST = 72;   // B smem stride (halfs)
    constexpr int CST = 68;   // C smem stride (floats), %4==0
    constexpr int SZ_AB = (128 * AST + 64 * BST) * 2;   // 27648
    constexpr int SZ_C  = 128 * CST * 4;                // 34816
    __shared__ __align__(16) char sm[SZ_C > SZ_AB ? SZ_C : SZ_AB];
    __shared__ float bs[64];

    __half* As = (__half*)sm;
    __half* Ws = (__half*)(sm + 128 * AST * 2);
    float*  Cs = (float*)sm;

    const int t = threadIdx.x;
    const int w = t >> 5;
    const int rowBase = blockIdx.x * 128;

    if (RELU && t < 64) bs[t] = bias[t];

    wmma::fragment<wmma::accumulator, 16, 16, 16, float> acc[4];
#pragma unroll
    for (int j = 0; j < 4; j++) wmma::fill_fragment(acc[j], 0.0f);

    for (int kc = 0; kc < K; kc += KC) {
        __syncthreads();    // bs ready (iter 0) / smem safe to overwrite (iter >0)
        // A chunk: 128 rows x 64 k, fp32 -> fp16. 2048 float4, 8 per thread.
#pragma unroll
        for (int i = 0; i < 8; i++) {
            int lin = i * 256 + t;
            int r = lin >> 4, f4 = lin & 15;
            int row = rowBase + r;
            float4 v = make_float4(0.f, 0.f, 0.f, 0.f);
            if (row < N) v = *(const float4*)&A[(size_t)row * K + kc + f4 * 4];
            if (RELU) {   // K==64 -> kc==0, col = f4*4+j
                v.x = fmaxf(v.x + bs[f4 * 4 + 0], 0.f);
                v.y = fmaxf(v.y + bs[f4 * 4 + 1], 0.f);
                v.z = fmaxf(v.z + bs[f4 * 4 + 2], 0.f);
                v.w = fmaxf(v.w + bs[f4 * 4 + 3], 0.f);
            }
            *(__half2*)&As[r * AST + f4 * 4]     = __floats2half2_rn(v.x, v.y);
            *(__half2*)&As[r * AST + f4 * 4 + 2] = __floats2half2_rn(v.z, v.w);
        }
        // B chunk: 64 k x 64 n fp32 row-major -> Ws[n*BST + k] (col-major for wmma)
#pragma unroll
        for (int i = 0; i < 4; i++) {
            int lin = i * 256 + t;
            int k = lin >> 4, f4 = lin & 15;
            float4 v = *(const float4*)&W[(size_t)(kc + k) * 64 + f4 * 4];
            Ws[(f4 * 4 + 0) * BST + k] = __float2half(v.x);
            Ws[(f4 * 4 + 1) * BST + k] = __float2half(v.y);
            Ws[(f4 * 4 + 2) * BST + k] = __float2half(v.z);
            Ws[(f4 * 4 + 3) * BST + k] = __float2half(v.w);
        }
        __syncthreads();

#pragma unroll
        for (int kk = 0; kk < KC; kk += 16) {
            wmma::fragment<wmma::matrix_a, 16, 16, 16, __half, wmma::row_major> af;
            wmma::load_matrix_sync(af, As + w * 16 * AST + kk, AST);
#pragma unroll
            for (int j = 0; j < 4; j++) {
                wmma::fragment<wmma::matrix_b, 16, 16, 16, __half, wmma::col_major> bf;
                wmma::load_matrix_sync(bf, Ws + j * 16 * BST + kk, BST);
                wmma::mma_sync(acc[j], af, bf, acc[j]);
            }
        }
    }

    __syncthreads();
#pragma unroll
    for (int j = 0; j < 4; j++)
        wmma::store_matrix_sync(Cs + w * 16 * CST + j * 16, acc[j], CST, wmma::mem_row_major);
    __syncthreads();

    // write d_gh fp16: 8192 floats, 8 float4 per thread
#pragma unroll
    for (int i = 0; i < 8; i++) {
        int lin = i * 256 + t;
        int r = lin >> 4, f4 = lin & 15;
        float4 v = *(const float4*)&Cs[r * CST + f4 * 4];
        __half2 h0 = __floats2half2_rn(v.x, v.y);
        __half2 h1 = __floats2half2_rn(v.z, v.w);
        uint2 u;
        u.x = *(unsigned*)&h0; u.y = *(unsigned*)&h1;
        *(uint2*)&d_gh[(size_t)(rowBase + r) * 64 + f4 * 4] = u;
    }
}

// ---------------- gather (layer 1): agg1[n] = dis[n]*(sum_s h[s]*dis[s] + h[n]*dis[n]) ----------------
__global__ void k_gather1(int N) {
    int idx = blockIdx.x * blockDim.x + threadIdx.x;
    int node = idx >> 4;
    if (node >= N) return;
    int c = (idx & 15) * 4;
    int beg = d_rowstart[node];
    int end = d_rowstart[node + 1];
    float dn = d_dis[node];
    float4 acc;
    {
        uint2 u = *(const uint2*)&d_gh[(size_t)node * 64 + c];
        float2 f0 = __half22float2(*(__half2*)&u.x);
        float2 f1 = __half22float2(*(__half2*)&u.y);
        acc = make_float4(f0.x * dn, f0.y * dn, f1.x * dn, f1.y * dn);
    }
    for (int e = beg; e < end; e++) {
        int s = d_csr[e];
        float ds = d_dis[s];
        uint2 u = *(const uint2*)&d_gh[(size_t)s * 64 + c];
        float2 f0 = __half22float2(*(__half2*)&u.x);
        float2 f1 = __half22float2(*(__half2*)&u.y);
        acc.x += f0.x * ds; acc.y += f0.y * ds;
        acc.z += f1.x * ds; acc.w += f1.y * ds;
    }
    *(float4*)&d_agg1[(size_t)node * 64 + c] =
        make_float4(acc.x * dn, acc.y * dn, acc.z * dn, acc.w * dn);
}

// ---------------- fused gather(layer2) + layer3 dot: no agg2 materialization ----------------
__global__ void k_g2l3(const float* __restrict__ W3, const float* __restrict__ b2v,
                       const float* __restrict__ b3, float* __restrict__ out, int N) {
    int idx = blockIdx.x * blockDim.x + threadIdx.x;
    int node = idx >> 4;
    if (node >= N) return;
    int lane = idx & 15;
    int c = lane * 4;
    float4 w3 = *(const float4*)&W3[c];
    float4 bb = *(const float4*)&b2v[c];
    int beg = d_rowstart[node];
    int end = d_rowstart[node + 1];
    float dn = d_dis[node];
    float4 acc;
    {
        uint2 u = *(const uint2*)&d_gh[(size_t)node * 64 + c];
        float2 f0 = __half22float2(*(__half2*)&u.x);
        float2 f1 = __half22float2(*(__half2*)&u.y);
        acc = make_float4(f0.x * dn, f0.y * dn, f1.x * dn, f1.y * dn);
    }
    for (int e = beg; e < end; e++) {
        int s = d_csr[e];
        float ds = d_dis[s];
        uint2 u = *(const uint2*)&d_gh[(size_t)s * 64 + c];
        float2 f0 = __half22float2(*(__half2*)&u.x);
        float2 f1 = __half22float2(*(__half2*)&u.y);
        acc.x += f0.x * ds; acc.y += f0.y * ds;
        acc.z += f1.x * ds; acc.w += f1.y * ds;
    }
    // agg2 value = acc * dn; layer3: relu(agg2 + b2) . W3
    float s = fmaxf(acc.x * dn + bb.x, 0.f) * w3.x
            + fmaxf(acc.y * dn + bb.y, 0.f) * w3.y
            + fmaxf(acc.z * dn + bb.z, 0.f) * w3.z
            + fmaxf(acc.w * dn + bb.w, 0.f) * w3.w;
    unsigned mask = 0xFFFFu << (threadIdx.x & 16);
    s += __shfl_xor_sync(mask, s, 1);
    s += __shfl_xor_sync(mask, s, 2);
    s += __shfl_xor_sync(mask, s, 4);
    s += __shfl_xor_sync(mask, s, 8);
    if (lane == 0) {
        d_g3[node] = s * dn;                 // premultiplied by dis[src]
        out[node]  = s * dn * dn + b3[0];
    }
}

__global__ void k_gather_out(float* __restrict__ out, int N) {
    int i = blockIdx.x * blockDim.x + threadIdx.x;
    if (i >= N) return;
    int beg = d_rowstart[i];
    int end = d_rowstart[i + 1];
    float s = 0.f;
    for (int e = beg; e < end; e++) s += d_g3[d_csr[e]];
    out[i] += s * d_dis[i];
}

// ---------------- launch ----------------
extern "C" void kernel_launch(void* const* d_in, const int* in_sizes, int n_in,
                              void* d_out, int out_size) {
    const float* x  = (const float*)d_in[0];
    const int*   ei = (const int*)d_in[1];        // int32 (JAX x64 disabled)
    const float* W1 = (const float*)d_in[2];
    const float* b1 = (const float*)d_in[3];
    const float* W2 = (const float*)d_in[4];
    const float* b2 = (const float*)d_in[5];
    const float* W3 = (const float*)d_in[6];
    const float* b3 = (const float*)d_in[7];
    float* out = (float*)d_out;

    int N = in_sizes[0] / 128;
    int E = in_sizes[1] / 2;

    static cudaStream_t s2 = nullptr;
    static cudaEvent_t ev_fork = nullptr, ev_gemm = nullptr;
    if (!s2) {
        cudaStreamCreateWithFlags(&s2, cudaStreamNonBlocking);
        cudaEventCreateWithFlags(&ev_fork, cudaEventDisableTiming);
        cudaEventCreateWithFlags(&ev_gemm, cudaEventDisableTiming);
    }

    const int gblocks = NPAD / 128;
    const int gather_blocks = (N * 16 + 255) / 256;

    // fork: GEMM1 (independent of graph preprocessing) on s2
    cudaEventRecord(ev_fork, 0);
    cudaStreamWaitEvent(s2, ev_fork, 0);
    k_gemm<128, false, 1><<<gblocks, 256, 0, s2>>>(x, W1, nullptr, N);
    cudaEventRecord(ev_gemm, s2);

    // preprocessing on the main stream: CSR by dst + norms
    k_count<<<(E + 255) / 256, 256>>>(ei, E, N);
    k_scan1<<<NBLK, 1024>>>();
    k_scan2<<<1, 128>>>();
    k_scan3<<<NBLK, 1024>>>();
    k_fill<<<(E + 255) / 256, 256>>>(ei, E, N);

    // join, then layer 1 aggregation
    cudaStreamWaitEvent(0, ev_gemm, 0);
    k_gather1<<<gather_blocks, 256>>>(N);

    // layer 2 transform (bias1+relu fused into A load)
    k_gemm<64, true, 2><<<gblocks, 256>>>(nullptr, W2, b1, NPAD);

    // fused layer-2 aggregation + layer-3 transform
    k_g2l3<<<gather_blocks, 256>>>(W3, b2, b3, out, N);

    // layer-3 aggregation
    k_gather_out<<<(N + 255) / 256, 256>>>(out, N);
}

// round 7
// speedup vs baseline: 2.2494x; 1.0083x over previous
#include <cuda_runtime.h>
#include <cuda_fp16.h>
#include <mma.h>

using namespace nvcuda;

#define NMAX  100000
#define NPAD  100352        // 1024 * 98, multiple of 128
#define NBLK  98            // NPAD / 1024
#define EMAX  1600000
#define HID   64

// ---------------- scratch (device globals; no allocation) ----------------
__device__ __align__(16) float  d_dis[NPAD];          // deg_inv_sqrt
__device__ __align__(16) __half d_gh[NPAD * HID];     // layer-1 h (fp16)
__device__ __align__(16) __half d_gh2[NPAD * HID];    // layer-2 h (fp16)
__device__ __align__(16) float  d_g3[NPAD];           // layer-3 h*dis
__device__ int d_csr[EMAX];                           // src ids grouped by dst
__device__ int d_cnt[NPAD];                           // indegree (zero-init; fill drains to 0)
__device__ int d_rowstart[NPAD + 1];                  // exclusive prefix of cnt
__device__ int d_bsum[NBLK];

// ---------------- preprocessing ----------------
__global__ void k_count(const int* __restrict__ ei, int E, int N) {
    int e = blockIdx.x * blockDim.x + threadIdx.x;
    if (e < E) {
        unsigned d = (unsigned)ei[E + e];
        if (d < (unsigned)N) atomicAdd(&d_cnt[d], 1);
    }
}

// phase 1: per-block reduce + fused dis
__global__ __launch_bounds__(1024) void k_scan1() {
    int b = blockIdx.x, t = threadIdx.x;
    int i = b * 1024 + t;
    int c = d_cnt[i];
    d_dis[i] = rsqrtf(1.0f + (float)c);
    __shared__ int sh[32];
    int v = c;
#pragma unroll
    for (int o = 16; o; o >>= 1) v += __shfl_down_sync(~0u, v, o);
    if ((t & 31) == 0) sh[t >> 5] = v;
    __syncthreads();
    if (t < 32) {
        int w = sh[t];
#pragma unroll
        for (int o = 16; o; o >>= 1) w += __shfl_down_sync(~0u, w, o);
        if (t == 0) d_bsum[b] = w;
    }
}

// phase 2 (merged): per-block scan of bsum for the offset + in-block exclusive scan
__global__ __launch_bounds__(1024) void k_scan3() {
    __shared__ int sh[1024];
    __shared__ int off[128];
    int b = blockIdx.x, t = threadIdx.x;
    int c = d_cnt[b * 1024 + t];
    sh[t] = c;
    if (t < 128) off[t] = (t < NBLK) ? d_bsum[t] : 0;
    __syncthreads();
    // scan the 98 block sums (inclusive) using the first 128 threads
    for (int o = 1; o < 128; o <<= 1) {
        int u = (t < 128 && t >= o) ? off[t - o] : 0;
        __syncthreads();
        if (t < 128) off[t] += u;
        __syncthreads();
    }
    int boff = off[b] - d_bsum[b];          // exclusive offset for this block
    // in-block inclusive scan of the 1024 counts
    for (int o = 1; o < 1024; o <<= 1) {
        int u = (t >= o) ? sh[t - o] : 0;
        __syncthreads();
        sh[t] += u;
        __syncthreads();
    }
    d_rowstart[b * 1024 + t] = boff + sh[t] - c;
    if (b == 0 && t == 0) d_rowstart[NPAD] = off[NBLK - 1];
}

// backward fill: drains d_cnt back to 0 (keeps the zero-on-entry invariant)
__global__ void k_fill(const int* __restrict__ ei, int E, int N) {
    int e = blockIdx.x * blockDim.x + threadIdx.x;
    if (e < E) {
        int s = ei[e];
        unsigned d = (unsigned)ei[E + e];
        if (d < (unsigned)N) {
            int pos = d_rowstart[d] + atomicSub(&d_cnt[d], 1) - 1;
            d_csr[pos] = s;
        }
    }
}

// ---------------- GEMM1: h1 = x(Nx128) @ W1(128x64) -> d_gh fp16 ----------------
// block: 256 threads (8 warps), tile 128 x 64. Warp w owns rows 16w..16w+15.
__global__ __launch_bounds__(256)
void k_gemm1(const float* __restrict__ A, const float* __restrict__ W, int N) {
    constexpr int K   = 128;
    constexpr int KC  = 64;
    constexpr int AST = 72;
    constexpr int BST = 72;
    constexpr int CST = 68;
    constexpr int SZ_AB = (128 * AST + 64 * BST) * 2;
    constexpr int SZ_C  = 128 * CST * 4;
    __shared__ __align__(16) char sm[SZ_C > SZ_AB ? SZ_C : SZ_AB];

    __half* As = (__half*)sm;
    __half* Ws = (__half*)(sm + 128 * AST * 2);
    float*  Cs = (float*)sm;

    const int t = threadIdx.x;
    const int w = t >> 5;
    const int rowBase = blockIdx.x * 128;

    wmma::fragment<wmma::accumulator, 16, 16, 16, float> acc[4];
#pragma unroll
    for (int j = 0; j < 4; j++) wmma::fill_fragment(acc[j], 0.0f);

    for (int kc = 0; kc < K; kc += KC) {
        __syncthreads();
#pragma unroll
        for (int i = 0; i < 8; i++) {
            int lin = i * 256 + t;
            int r = lin >> 4, f4 = lin & 15;
            int row = rowBase + r;
            float4 v = make_float4(0.f, 0.f, 0.f, 0.f);
            if (row < N) v = *(const float4*)&A[(size_t)row * K + kc + f4 * 4];
            *(__half2*)&As[r * AST + f4 * 4]     = __floats2half2_rn(v.x, v.y);
            *(__half2*)&As[r * AST + f4 * 4 + 2] = __floats2half2_rn(v.z, v.w);
        }
#pragma unroll
        for (int i = 0; i < 4; i++) {
            int lin = i * 256 + t;
            int k = lin >> 4, f4 = lin & 15;
            float4 v = *(const float4*)&W[(size_t)(kc + k) * 64 + f4 * 4];
            Ws[(f4 * 4 + 0) * BST + k] = __float2half(v.x);
            Ws[(f4 * 4 + 1) * BST + k] = __float2half(v.y);
            Ws[(f4 * 4 + 2) * BST + k] = __float2half(v.z);
            Ws[(f4 * 4 + 3) * BST + k] = __float2half(v.w);
        }
        __syncthreads();

#pragma unroll
        for (int kk = 0; kk < KC; kk += 16) {
            wmma::fragment<wmma::matrix_a, 16, 16, 16, __half, wmma::row_major> af;
            wmma::load_matrix_sync(af, As + w * 16 * AST + kk, AST);
#pragma unroll
            for (int j = 0; j < 4; j++) {
                wmma::fragment<wmma::matrix_b, 16, 16, 16, __half, wmma::col_major> bf;
                wmma::load_matrix_sync(bf, Ws + j * 16 * BST + kk, BST);
                wmma::mma_sync(acc[j], af, bf, acc[j]);
            }
        }
    }

    __syncthreads();
#pragma unroll
    for (int j = 0; j < 4; j++)
        wmma::store_matrix_sync(Cs + w * 16 * CST + j * 16, acc[j], CST, wmma::mem_row_major);
    __syncthreads();

#pragma unroll
    for (int i = 0; i < 8; i++) {
        int lin = i * 256 + t;
        int r = lin >> 4, f4 = lin & 15;
        float4 v = *(const float4*)&Cs[r * CST + f4 * 4];
        __half2 h0 = __floats2half2_rn(v.x, v.y);
        __half2 h1 = __floats2half2_rn(v.z, v.w);
        uint2 u;
        u.x = *(unsigned*)&h0; u.y = *(unsigned*)&h1;
        *(uint2*)&d_gh[(size_t)(rowBase + r) * 64 + f4 * 4] = u;
    }
}

// ---------------- fused gather(layer1) + GEMM2: d_gh2 = relu(agg1 + b1) @ W2 ----------------
// Gathers neighbor sums straight into the fp16 A-tile in smem, then HMMA.
__global__ __launch_bounds__(256)
void k_gg2(const float* __restrict__ W, const float* __restrict__ b1) {
    constexpr int AST = 72;
    constexpr int BST = 72;
    constexpr int CST = 68;
    constexpr int SZ_AB = (128 * AST + 64 * BST) * 2;
    constexpr int SZ_C  = 128 * CST * 4;
    __shared__ __align__(16) char sm[SZ_C > SZ_AB ? SZ_C : SZ_AB];

    __half* As = (__half*)sm;
    __half* Ws = (__half*)(sm + 128 * AST * 2);
    float*  Cs = (float*)sm;

    const int t = threadIdx.x;
    const int w = t >> 5;
    const int lane = t & 31;
    const int sub = lane >> 4;            // 0/1: which node within the warp
    const int c = (lane & 15) * 4;        // feature offset (halfs)
    const int rowBase = blockIdx.x * 128;

    const float4 bb = *(const float4*)&b1[c];

    // gather stage: 8 passes, 2 nodes per warp per pass -> 128 rows
#pragma unroll 1
    for (int pass = 0; pass < 8; pass++) {
        int r = pass * 16 + w * 2 + sub;
        int node = rowBase + r;           // < NPAD always; ranges empty for node >= N
        int beg = d_rowstart[node];
        int end = d_rowstart[node + 1];
        float dn = d_dis[node];
        float4 acc;
        {
            uint2 u = *(const uint2*)&d_gh[(size_t)node * 64 + c];
            float2 f0 = __half22float2(*(__half2*)&u.x);
            float2 f1 = __half22float2(*(__half2*)&u.y);
            acc = make_float4(f0.x * dn, f0.y * dn, f1.x * dn, f1.y * dn);
        }
        for (int e = beg; e < end; e++) {
            int s = d_csr[e];
            float ds = d_dis[s];
            uint2 u = *(const uint2*)&d_gh[(size_t)s * 64 + c];
            float2 f0 = __half22float2(*(__half2*)&u.x);
            float2 f1 = __half22float2(*(__half2*)&u.y);
            acc.x += f0.x * ds; acc.y += f0.y * ds;
            acc.z += f1.x * ds; acc.w += f1.y * ds;
        }
        // agg1 = acc*dn ; A = relu(agg1 + b1), fp16
        float vx = fmaxf(acc.x * dn + bb.x, 0.f);
        float vy = fmaxf(acc.y * dn + bb.y, 0.f);
        float vz = fmaxf(acc.z * dn + bb.z, 0.f);
        float vw = fmaxf(acc.w * dn + bb.w, 0.f);
        __half2 h0 = __floats2half2_rn(vx, vy);
        __half2 h1 = __floats2half2_rn(vz, vw);
        uint2 u;
        u.x = *(unsigned*)&h0; u.y = *(unsigned*)&h1;
        *(uint2*)&As[r * AST + c] = u;
    }

    // W2 tile: 64 k x 64 n -> col-major Ws
#pragma unroll
    for (int i = 0; i < 4; i++) {
        int lin = i * 256 + t;
        int k = lin >> 4, f4 = lin & 15;
        float4 v = *(const float4*)&W[(size_t)k * 64 + f4 * 4];
        Ws[(f4 * 4 + 0) * BST + k] = __float2half(v.x);
        Ws[(f4 * 4 + 1) * BST + k] = __float2half(v.y);
        Ws[(f4 * 4 + 2) * BST + k] = __float2half(v.z);
        Ws[(f4 * 4 + 3) * BST + k] = __float2half(v.w);
    }
    __syncthreads();

    wmma::fragment<wmma::accumulator, 16, 16, 16, float> acc[4];
#pragma unroll
    for (int j = 0; j < 4; j++) wmma::fill_fragment(acc[j], 0.0f);

#pragma unroll
    for (int kk = 0; kk < 64; kk += 16) {
        wmma::fragment<wmma::matrix_a, 16, 16, 16, __half, wmma::row_major> af;
        wmma::load_matrix_sync(af, As + w * 16 * AST + kk, AST);
#pragma unroll
        for (int j = 0; j < 4; j++) {
            wmma::fragment<wmma::matrix_b, 16, 16, 16, __half, wmma::col_major> bf;
            wmma::load_matrix_sync(bf, Ws + j * 16 * BST + kk, BST);
            wmma::mma_sync(acc[j], af, bf, acc[j]);
        }
    }

    __syncthreads();
#pragma unroll
    for (int j = 0; j < 4; j++)
        wmma::store_matrix_sync(Cs + w * 16 * CST + j * 16, acc[j], CST, wmma::mem_row_major);
    __syncthreads();

#pragma unroll
    for (int i = 0; i < 8; i++) {
        int lin = i * 256 + t;
        int r = lin >> 4, f4 = lin & 15;
        float4 v = *(const float4*)&Cs[r * CST + f4 * 4];
        __half2 h0 = __floats2half2_rn(v.x, v.y);
        __half2 h1 = __floats2half2_rn(v.z, v.w);
        uint2 u;
        u.x = *(unsigned*)&h0; u.y = *(unsigned*)&h1;
        *(uint2*)&d_gh2[(size_t)(rowBase + r) * 64 + f4 * 4] = u;
    }
}

// ---------------- fused gather(layer2) + layer3 dot ----------------
__global__ void k_g2l3(const float* __restrict__ W3, const float* __restrict__ b2v,
                       const float* __restrict__ b3, float* __restrict__ out, int N) {
    int idx = blockIdx.x * blockDim.x + threadIdx.x;
    int node = idx >> 4;
    if (node >= N) return;
    int lane = idx & 15;
    int c = lane * 4;
    float4 w3 = *(const float4*)&W3[c];
    float4 bb = *(const float4*)&b2v[c];
    int beg = d_rowstart[node];
    int end = d_rowstart[node + 1];
    float dn = d_dis[node];
    float4 acc;
    {
        uint2 u = *(const uint2*)&d_gh2[(size_t)node * 64 + c];
        float2 f0 = __half22float2(*(__half2*)&u.x);
        float2 f1 = __half22float2(*(__half2*)&u.y);
        acc = make_float4(f0.x * dn, f0.y * dn, f1.x * dn, f1.y * dn);
    }
    for (int e = beg; e < end; e++) {
        int s = d_csr[e];
        float ds = d_dis[s];
        uint2 u = *(const uint2*)&d_gh2[(size_t)s * 64 + c];
        float2 f0 = __half22float2(*(__half2*)&u.x);
        float2 f1 = __half22float2(*(__half2*)&u.y);
        acc.x += f0.x * ds; acc.y += f0.y * ds;
        acc.z += f1.x * ds; acc.w += f1.y * ds;
    }
    float s = fmaxf(acc.x * dn + bb.x, 0.f) * w3.x
            + fmaxf(acc.y * dn + bb.y, 0.f) * w3.y
            + fmaxf(acc.z * dn + bb.z, 0.f) * w3.z
            + fmaxf(acc.w * dn + bb.w, 0.f) * w3.w;
    unsigned mask = 0xFFFFu << (threadIdx.x & 16);
    s += __shfl_xor_sync(mask, s, 1);
    s += __shfl_xor_sync(mask, s, 2);
    s += __shfl_xor_sync(mask, s, 4);
    s += __shfl_xor_sync(mask, s, 8);
    if (lane == 0) {
        d_g3[node] = s * dn;                 // premultiplied by dis[src]
        out[node]  = s * dn * dn + b3[0];
    }
}

__global__ void k_gather_out(float* __restrict__ out, int N) {
    int i = blockIdx.x * blockDim.x + threadIdx.x;
    if (i >= N) return;
    int beg = d_rowstart[i];
    int end = d_rowstart[i + 1];
    float s = 0.f;
    for (int e = beg; e < end; e++) s += d_g3[d_csr[e]];
    out[i] += s * d_dis[i];
}

// ---------------- launch ----------------
extern "C" void kernel_launch(void* const* d_in, const int* in_sizes, int n_in,
                              void* d_out, int out_size) {
    const float* x  = (const float*)d_in[0];
    const int*   ei = (const int*)d_in[1];        // int32 (JAX x64 disabled)
    const float* W1 = (const float*)d_in[2];
    const float* b1 = (const float*)d_in[3];
    const float* W2 = (const float*)d_in[4];
    const float* b2 = (const float*)d_in[5];
    const float* W3 = (const float*)d_in[6];
    const float* b3 = (const float*)d_in[7];
    float* out = (float*)d_out;

    int N = in_sizes[0] / 128;
    int E = in_sizes[1] / 2;

    static cudaStream_t s2 = nullptr;
    static cudaEvent_t ev_fork = nullptr, ev_gemm = nullptr;
    if (!s2) {
        cudaStreamCreateWithFlags(&s2, cudaStreamNonBlocking);
        cudaEventCreateWithFlags(&ev_fork, cudaEventDisableTiming);
        cudaEventCreateWithFlags(&ev_gemm, cudaEventDisableTiming);
    }

    const int gblocks = NPAD / 128;
    const int gather_blocks = (N * 16 + 255) / 256;

    // fork: GEMM1 (independent of graph preprocessing) on s2
    cudaEventRecord(ev_fork, 0);
    cudaStreamWaitEvent(s2, ev_fork, 0);
    k_gemm1<<<gblocks, 256, 0, s2>>>(x, W1, N);
    cudaEventRecord(ev_gemm, s2);

    // preprocessing on the main stream: CSR by dst + norms
    k_count<<<(E + 255) / 256, 256>>>(ei, E, N);
    k_scan1<<<NBLK, 1024>>>();
    k_scan3<<<NBLK, 1024>>>();
    k_fill<<<(E + 255) / 256, 256>>>(ei, E, N);

    // join, then fused layer-1 aggregation + layer-2 transform
    cudaStreamWaitEvent(0, ev_gemm, 0);
    k_gg2<<<gblocks, 256>>>(W2, b1);

    // fused layer-2 aggregation + layer-3 transform
    k_g2l3<<<gather_blocks, 256>>>(W3, b2, b3, out, N);

    // layer-3 aggregation
    k_gather_out<<<(N + 255) / 256, 256>>>(out, N);
}

// round 8
// speedup vs baseline: 2.2663x; 1.0075x over previous
#include <cuda_runtime.h>
#include <cuda_fp16.h>
#include <mma.h>

using namespace nvcuda;

#define NMAX  100000
#define NPAD  100352        // 1024 * 98, multiple of 128
#define NBLK  98            // NPAD / 1024
#define EMAX  1600000
#define HID   64

// ---------------- scratch (device globals; no allocation) ----------------
__device__ __align__(16) float  d_dis[NPAD];          // deg_inv_sqrt
__device__ __align__(16) __half d_gh[NPAD * HID];     // layer-1 h (fp16, raw)
__device__ __align__(16) __half d_gh2[NPAD * HID];    // layer-2 h * dis (fp16, premultiplied)
__device__ __align__(16) float  d_g3[NPAD];           // layer-3 h*dis
__device__ int d_csr[EMAX];                           // src ids grouped by dst
__device__ int d_cnt[NPAD];                           // indegree (zero-init; fill drains to 0)
__device__ int d_rowstart[NPAD + 1];                  // exclusive prefix of cnt
__device__ int d_bsum[NBLK];

// ---------------- preprocessing ----------------
__global__ void k_count(const int* __restrict__ ei, int E, int N) {
    int e = blockIdx.x * blockDim.x + threadIdx.x;
    if (e < E) {
        unsigned d = (unsigned)ei[E + e];
        if (d < (unsigned)N) atomicAdd(&d_cnt[d], 1);
    }
}

__global__ __launch_bounds__(1024) void k_scan1() {
    int b = blockIdx.x, t = threadIdx.x;
    int i = b * 1024 + t;
    int c = d_cnt[i];
    d_dis[i] = rsqrtf(1.0f + (float)c);
    __shared__ int sh[32];
    int v = c;
#pragma unroll
    for (int o = 16; o; o >>= 1) v += __shfl_down_sync(~0u, v, o);
    if ((t & 31) == 0) sh[t >> 5] = v;
    __syncthreads();
    if (t < 32) {
        int w = sh[t];
#pragma unroll
        for (int o = 16; o; o >>= 1) w += __shfl_down_sync(~0u, w, o);
        if (t == 0) d_bsum[b] = w;
    }
}

__global__ __launch_bounds__(1024) void k_scan3() {
    __shared__ int sh[1024];
    __shared__ int off[128];
    int b = blockIdx.x, t = threadIdx.x;
    int c = d_cnt[b * 1024 + t];
    sh[t] = c;
    if (t < 128) off[t] = (t < NBLK) ? d_bsum[t] : 0;
    __syncthreads();
    for (int o = 1; o < 128; o <<= 1) {
        int u = (t < 128 && t >= o) ? off[t - o] : 0;
        __syncthreads();
        if (t < 128) off[t] += u;
        __syncthreads();
    }
    int boff = off[b] - d_bsum[b];
    for (int o = 1; o < 1024; o <<= 1) {
        int u = (t >= o) ? sh[t - o] : 0;
        __syncthreads();
        sh[t] += u;
        __syncthreads();
    }
    d_rowstart[b * 1024 + t] = boff + sh[t] - c;
    if (b == 0 && t == 0) d_rowstart[NPAD] = off[NBLK - 1];
}

__global__ void k_fill(const int* __restrict__ ei, int E, int N) {
    int e = blockIdx.x * blockDim.x + threadIdx.x;
    if (e < E) {
        int s = ei[e];
        unsigned d = (unsigned)ei[E + e];
        if (d < (unsigned)N) {
            int pos = d_rowstart[d] + atomicSub(&d_cnt[d], 1) - 1;
            d_csr[pos] = s;
        }
    }
}

// ---------------- GEMM1: h1 = x(Nx128) @ W1(128x64) -> d_gh fp16 (raw) ----------------
__global__ __launch_bounds__(256)
void k_gemm1(const float* __restrict__ A, const float* __restrict__ W, int N) {
    constexpr int K   = 128;
    constexpr int KC  = 64;
    constexpr int AST = 72;
    constexpr int BST = 72;
    constexpr int CST = 68;
    constexpr int SZ_AB = (128 * AST + 64 * BST) * 2;
    constexpr int SZ_C  = 128 * CST * 4;
    __shared__ __align__(16) char sm[SZ_C > SZ_AB ? SZ_C : SZ_AB];

    __half* As = (__half*)sm;
    __half* Ws = (__half*)(sm + 128 * AST * 2);
    float*  Cs = (float*)sm;

    const int t = threadIdx.x;
    const int w = t >> 5;
    const int rowBase = blockIdx.x * 128;

    wmma::fragment<wmma::accumulator, 16, 16, 16, float> acc[4];
#pragma unroll
    for (int j = 0; j < 4; j++) wmma::fill_fragment(acc[j], 0.0f);

    for (int kc = 0; kc < K; kc += KC) {
        __syncthreads();
#pragma unroll
        for (int i = 0; i < 8; i++) {
            int lin = i * 256 + t;
            int r = lin >> 4, f4 = lin & 15;
            int row = rowBase + r;
            float4 v = make_float4(0.f, 0.f, 0.f, 0.f);
            if (row < N) v = *(const float4*)&A[(size_t)row * K + kc + f4 * 4];
            *(__half2*)&As[r * AST + f4 * 4]     = __floats2half2_rn(v.x, v.y);
            *(__half2*)&As[r * AST + f4 * 4 + 2] = __floats2half2_rn(v.z, v.w);
        }
#pragma unroll
        for (int i = 0; i < 4; i++) {
            int lin = i * 256 + t;
            int k = lin >> 4, f4 = lin & 15;
            float4 v = *(const float4*)&W[(size_t)(kc + k) * 64 + f4 * 4];
            Ws[(f4 * 4 + 0) * BST + k] = __float2half(v.x);
            Ws[(f4 * 4 + 1) * BST + k] = __float2half(v.y);
            Ws[(f4 * 4 + 2) * BST + k] = __float2half(v.z);
            Ws[(f4 * 4 + 3) * BST + k] = __float2half(v.w);
        }
        __syncthreads();

#pragma unroll
        for (int kk = 0; kk < KC; kk += 16) {
            wmma::fragment<wmma::matrix_a, 16, 16, 16, __half, wmma::row_major> af;
            wmma::load_matrix_sync(af, As + w * 16 * AST + kk, AST);
#pragma unroll
            for (int j = 0; j < 4; j++) {
                wmma::fragment<wmma::matrix_b, 16, 16, 16, __half, wmma::col_major> bf;
                wmma::load_matrix_sync(bf, Ws + j * 16 * BST + kk, BST);
                wmma::mma_sync(acc[j], af, bf, acc[j]);
            }
        }
    }

    __syncthreads();
#pragma unroll
    for (int j = 0; j < 4; j++)
        wmma::store_matrix_sync(Cs + w * 16 * CST + j * 16, acc[j], CST, wmma::mem_row_major);
    __syncthreads();

#pragma unroll
    for (int i = 0; i < 8; i++) {
        int lin = i * 256 + t;
        int r = lin >> 4, f4 = lin & 15;
        float4 v = *(const float4*)&Cs[r * CST + f4 * 4];
        __half2 h0 = __floats2half2_rn(v.x, v.y);
        __half2 h1 = __floats2half2_rn(v.z, v.w);
        uint2 u;
        u.x = *(unsigned*)&h0; u.y = *(unsigned*)&h1;
        *(uint2*)&d_gh[(size_t)(rowBase + r) * 64 + f4 * 4] = u;
    }
}

// ---------------- fused gather(layer1) + GEMM2 -> d_gh2 = (relu(agg1+b1) @ W2) * dis ----------------
// gather: 8 lanes/node, uint4 (16B) per lane; 2-wide unrolled edge loop.
__global__ __launch_bounds__(256)
void k_gg2(const float* __restrict__ W, const float* __restrict__ b1) {
    constexpr int AST = 72;   // halfs; 144B row, %16==0 -> uint4 stores OK
    constexpr int BST = 72;
    constexpr int CST = 68;
    constexpr int SZ_AB = (128 * AST + 64 * BST) * 2;
    constexpr int SZ_C  = 128 * CST * 4;
    __shared__ __align__(16) char sm[SZ_C > SZ_AB ? SZ_C : SZ_AB];

    __half* As = (__half*)sm;
    __half* Ws = (__half*)(sm + 128 * AST * 2);
    float*  Cs = (float*)sm;

    const int t = threadIdx.x;
    const int w = t >> 5;
    const int lane = t & 31;
    const int sub = lane >> 3;            // 0..3: node within warp
    const int c = (lane & 7) * 8;         // half offset within row
    const int rowBase = blockIdx.x * 128;

    float bb[8];
    {
        float4 b0 = *(const float4*)&b1[c];
        float4 b4 = *(const float4*)&b1[c + 4];
        bb[0]=b0.x; bb[1]=b0.y; bb[2]=b0.z; bb[3]=b0.w;
        bb[4]=b4.x; bb[5]=b4.y; bb[6]=b4.z; bb[7]=b4.w;
    }

    // gather stage: 4 passes, 4 nodes per warp per pass -> 128 rows
#pragma unroll 1
    for (int pass = 0; pass < 4; pass++) {
        int r = pass * 32 + w * 4 + sub;
        int node = rowBase + r;
        int beg = d_rowstart[node];
        int end = d_rowstart[node + 1];
        float dn = d_dis[node];
        float acc[8];
        {
            uint4 u = *(const uint4*)&d_gh[(size_t)node * 64 + c];
            const __half2* h = (const __half2*)&u;
#pragma unroll
            for (int i = 0; i < 4; i++) {
                float2 f = __half22float2(h[i]);
                acc[i * 2] = f.x * dn; acc[i * 2 + 1] = f.y * dn;
            }
        }
        int e = beg;
        for (; e + 1 < end; e += 2) {
            int s0 = d_csr[e], s1 = d_csr[e + 1];
            float ds0 = d_dis[s0], ds1 = d_dis[s1];
            uint4 u0 = *(const uint4*)&d_gh[(size_t)s0 * 64 + c];
            uint4 u1 = *(const uint4*)&d_gh[(size_t)s1 * 64 + c];
            const __half2* h0 = (const __half2*)&u0;
            const __half2* h1 = (const __half2*)&u1;
#pragma unroll
            for (int i = 0; i < 4; i++) {
                float2 f0 = __half22float2(h0[i]);
                float2 f1 = __half22float2(h1[i]);
                acc[i * 2]     += f0.x * ds0 + f1.x * ds1;
                acc[i * 2 + 1] += f0.y * ds0 + f1.y * ds1;
            }
        }
        if (e < end) {
            int s0 = d_csr[e];
            float ds0 = d_dis[s0];
            uint4 u0 = *(const uint4*)&d_gh[(size_t)s0 * 64 + c];
            const __half2* h0 = (const __half2*)&u0;
#pragma unroll
            for (int i = 0; i < 4; i++) {
                float2 f0 = __half22float2(h0[i]);
                acc[i * 2]     += f0.x * ds0;
                acc[i * 2 + 1] += f0.y * ds0;
            }
        }
        // A = relu(acc*dn + b1), fp16
        __half2 hh[4];
#pragma unroll
        for (int i = 0; i < 4; i++)
            hh[i] = __floats2half2_rn(fmaxf(acc[i * 2] * dn + bb[i * 2], 0.f),
                                      fmaxf(acc[i * 2 + 1] * dn + bb[i * 2 + 1], 0.f));
        *(uint4*)&As[r * AST + c] = *(uint4*)hh;
    }

    // W2 tile: 64 k x 64 n -> col-major Ws
#pragma unroll
    for (int i = 0; i < 4; i++) {
        int lin = i * 256 + t;
        int k = lin >> 4, f4 = lin & 15;
        float4 v = *(const float4*)&W[(size_t)k * 64 + f4 * 4];
        Ws[(f4 * 4 + 0) * BST + k] = __float2half(v.x);
        Ws[(f4 * 4 + 1) * BST + k] = __float2half(v.y);
        Ws[(f4 * 4 + 2) * BST + k] = __float2half(v.z);
        Ws[(f4 * 4 + 3) * BST + k] = __float2half(v.w);
    }
    __syncthreads();

    wmma::fragment<wmma::accumulator, 16, 16, 16, float> acc[4];
#pragma unroll
    for (int j = 0; j < 4; j++) wmma::fill_fragment(acc[j], 0.0f);

#pragma unroll
    for (int kk = 0; kk < 64; kk += 16) {
        wmma::fragment<wmma::matrix_a, 16, 16, 16, __half, wmma::row_major> af;
        wmma::load_matrix_sync(af, As + w * 16 * AST + kk, AST);
#pragma unroll
        for (int j = 0; j < 4; j++) {
            wmma::fragment<wmma::matrix_b, 16, 16, 16, __half, wmma::col_major> bf;
            wmma::load_matrix_sync(bf, Ws + j * 16 * BST + kk, BST);
            wmma::mma_sync(acc[j], af, bf, acc[j]);
        }
    }

    __syncthreads();
#pragma unroll
    for (int j = 0; j < 4; j++)
        wmma::store_matrix_sync(Cs + w * 16 * CST + j * 16, acc[j], CST, wmma::mem_row_major);
    __syncthreads();

    // epilogue: gh2 = h2 * dis  (premultiplied for downstream gathers)
#pragma unroll
    for (int i = 0; i < 8; i++) {
        int lin = i * 256 + t;
        int r = lin >> 4, f4 = lin & 15;
        float dn = d_dis[rowBase + r];
        float4 v = *(const float4*)&Cs[r * CST + f4 * 4];
        __half2 h0 = __floats2half2_rn(v.x * dn, v.y * dn);
        __half2 h1 = __floats2half2_rn(v.z * dn, v.w * dn);
        uint2 u;
        u.x = *(unsigned*)&h0; u.y = *(unsigned*)&h1;
        *(uint2*)&d_gh2[(size_t)(rowBase + r) * 64 + f4 * 4] = u;
    }
}

// ---------------- fused gather(layer2) + layer3 dot; gh2 premultiplied by dis ----------------
// 8 lanes/node, uint4 per lane, 2-wide unrolled edge loop.
__global__ void k_g2l3(const float* __restrict__ W3, const float* __restrict__ b2v,
                       const float* __restrict__ b3, float* __restrict__ out, int N) {
    int idx = blockIdx.x * blockDim.x + threadIdx.x;
    int node = idx >> 3;
    if (node >= N) return;
    int lane = idx & 7;
    int c = lane * 8;
    float w3[8], bb[8];
    {
        float4 a = *(const float4*)&W3[c];
        float4 b = *(const float4*)&W3[c + 4];
        w3[0]=a.x; w3[1]=a.y; w3[2]=a.z; w3[3]=a.w;
        w3[4]=b.x; w3[5]=b.y; w3[6]=b.z; w3[7]=b.w;
        float4 p = *(const float4*)&b2v[c];
        float4 q = *(const float4*)&b2v[c + 4];
        bb[0]=p.x; bb[1]=p.y; bb[2]=p.z; bb[3]=p.w;
        bb[4]=q.x; bb[5]=q.y; bb[6]=q.z; bb[7]=q.w;
    }
    int beg = d_rowstart[node];
    int end = d_rowstart[node + 1];
    float dn = d_dis[node];
    float acc[8];
    {
        uint4 u = *(const uint4*)&d_gh2[(size_t)node * 64 + c];
        const __half2* h = (const __half2*)&u;
#pragma unroll
        for (int i = 0; i < 4; i++) {
            float2 f = __half22float2(h[i]);
            acc[i * 2] = f.x; acc[i * 2 + 1] = f.y;
        }
    }
    int e = beg;
    for (; e + 1 < end; e += 2) {
        int s0 = d_csr[e], s1 = d_csr[e + 1];
        uint4 u0 = *(const uint4*)&d_gh2[(size_t)s0 * 64 + c];
        uint4 u1 = *(const uint4*)&d_gh2[(size_t)s1 * 64 + c];
        const __half2* h0 = (const __half2*)&u0;
        const __half2* h1 = (const __half2*)&u1;
#pragma unroll
        for (int i = 0; i < 4; i++) {
            float2 f0 = __half22float2(h0[i]);
            float2 f1 = __half22float2(h1[i]);
            acc[i * 2]     += f0.x + f1.x;
            acc[i * 2 + 1] += f0.y + f1.y;
        }
    }
    if (e < end) {
        int s0 = d_csr[e];
        uint4 u0 = *(const uint4*)&d_gh2[(size_t)s0 * 64 + c];
        const __half2* h0 = (const __half2*)&u0;
#pragma unroll
        for (int i = 0; i < 4; i++) {
            float2 f0 = __half22float2(h0[i]);
            acc[i * 2]     += f0.x;
            acc[i * 2 + 1] += f0.y;
        }
    }
    float s = 0.f;
#pragma unroll
    for (int i = 0; i < 8; i++)
        s += fmaxf(acc[i] * dn + bb[i], 0.f) * w3[i];
    unsigned mask = 0xFFu << (threadIdx.x & 24);
    s += __shfl_xor_sync(mask, s, 1);
    s += __shfl_xor_sync(mask, s, 2);
    s += __shfl_xor_sync(mask, s, 4);
    if (lane == 0) {
        d_g3[node] = s * dn;                 // premultiplied by dis[src]
        out[node]  = s * dn * dn + b3[0];
    }
}

__global__ void k_gather_out(float* __restrict__ out, int N) {
    int i = blockIdx.x * blockDim.x + threadIdx.x;
    if (i >= N) return;
    int beg = d_rowstart[i];
    int end = d_rowstart[i + 1];
    float s0 = 0.f, s1 = 0.f;
    int e = beg;
    for (; e + 1 < end; e += 2) {
        s0 += d_g3[d_csr[e]];
        s1 += d_g3[d_csr[e + 1]];
    }
    if (e < end) s0 += d_g3[d_csr[e]];
    out[i] += (s0 + s1) * d_dis[i];
}

// ---------------- launch ----------------
extern "C" void kernel_launch(void* const* d_in, const int* in_sizes, int n_in,
                              void* d_out, int out_size) {
    const float* x  = (const float*)d_in[0];
    const int*   ei = (const int*)d_in[1];        // int32 (JAX x64 disabled)
    const float* W1 = (const float*)d_in[2];
    const float* b1 = (const float*)d_in[3];
    const float* W2 = (const float*)d_in[4];
    const float* b2 = (const float*)d_in[5];
    const float* W3 = (const float*)d_in[6];
    const float* b3 = (const float*)d_in[7];
    float* out = (float*)d_out;

    int N = in_sizes[0] / 128;
    int E = in_sizes[1] / 2;

    static cudaStream_t s2 = nullptr;
    static cudaEvent_t ev_fork = nullptr, ev_gemm = nullptr;
    if (!s2) {
        cudaStreamCreateWithFlags(&s2, cudaStreamNonBlocking);
        cudaEventCreateWithFlags(&ev_fork, cudaEventDisableTiming);
        cudaEventCreateWithFlags(&ev_gemm, cudaEventDisableTiming);
    }

    const int gblocks = NPAD / 128;

    // fork: GEMM1 (independent of graph preprocessing) on s2
    cudaEventRecord(ev_fork, 0);
    cudaStreamWaitEvent(s2, ev_fork, 0);
    k_gemm1<<<gblocks, 256, 0, s2>>>(x, W1, N);
    cudaEventRecord(ev_gemm, s2);

    // preprocessing on the main stream: CSR by dst + norms
    k_count<<<(E + 255) / 256, 256>>>(ei, E, N);
    k_scan1<<<NBLK, 1024>>>();
    k_scan3<<<NBLK, 1024>>>();
    k_fill<<<(E + 255) / 256, 256>>>(ei, E, N);

    // join, then fused layer-1 aggregation + layer-2 transform
    cudaStreamWaitEvent(0, ev_gemm, 0);
    k_gg2<<<gblocks, 256>>>(W2, b1);

    // fused layer-2 aggregation + layer-3 transform
    k_g2l3<<<(N * 8 + 255) / 256, 256>>>(W3, b2, b3, out, N);

    // layer-3 aggregation
    k_gather_out<<<(N + 255) / 256, 256>>>(out, N);
}

// round 9
// speedup vs baseline: 2.3840x; 1.0520x over previous
#include <cuda_runtime.h>
#include <cuda_fp16.h>
#include <mma.h>

using namespace nvcuda;

#define NMAX  100000
#define NPAD  100352        // 1024 * 98, multiple of 128
#define NBLK  98            // NPAD / 1024
#define EMAX  1600000
#define HID   64

#define LB_AGG (1ULL << 32)
#define LB_PRE (2ULL << 32)

// ---------------- scratch (device globals; no allocation) ----------------
__device__ __align__(16) float  d_dis[NPAD];          // deg_inv_sqrt
__device__ __align__(16) __half d_gh[NPAD * HID];     // layer-1 h (fp16, raw)
__device__ __align__(16) __half d_gh2[NPAD * HID];    // layer-2 h * dis (fp16, premultiplied)
__device__ __align__(16) float  d_g3[NPAD];           // layer-3 h*dis
__device__ int d_csr[EMAX];                           // src ids grouped by dst
__device__ int d_cnt[NPAD];                           // indegree (zero-init; fill drains to 0)
__device__ int d_rowstart[NPAD + 1];                  // exclusive prefix of cnt
__device__ unsigned long long d_lb[NBLK];             // decoupled-lookback state

// ---------------- preprocessing ----------------
__global__ void k_count(const int* __restrict__ ei, int E, int N) {
    if (blockIdx.x == 0 && threadIdx.x < NBLK) d_lb[threadIdx.x] = 0;   // reset lookback state
    int e = blockIdx.x * blockDim.x + threadIdx.x;
    if (e < E) {
        unsigned d = (unsigned)ei[E + e];
        if (d < (unsigned)N) atomicAdd(&d_cnt[d], 1);
    }
}

// single-pass scan: per-block reduce -> publish -> in-block scan -> lookback -> rowstart + dis
__global__ __launch_bounds__(1024) void k_scan() {
    __shared__ int sh[1024];
    __shared__ int s_ws[32];
    __shared__ int s_total;
    __shared__ int s_prefix;
    int b = blockIdx.x, t = threadIdx.x;
    int i = b * 1024 + t;
    int c = d_cnt[i];
    d_dis[i] = rsqrtf(1.0f + (float)c);

    // block total
    int v = c;
#pragma unroll
    for (int o = 16; o; o >>= 1) v += __shfl_down_sync(~0u, v, o);
    if ((t & 31) == 0) s_ws[t >> 5] = v;
    __syncthreads();
    if (t < 32) {
        int w = s_ws[t];
#pragma unroll
        for (int o = 16; o; o >>= 1) w += __shfl_down_sync(~0u, w, o);
        if (t == 0) {
            s_total = w;
            unsigned long long pub = (b == 0) ? (LB_PRE | (unsigned)w) : (LB_AGG | (unsigned)w);
            atomicExch(&d_lb[b], pub);
        }
    }
    // in-block inclusive scan
    sh[t] = c;
    __syncthreads();
    for (int o = 1; o < 1024; o <<= 1) {
        int u = (t >= o) ? sh[t - o] : 0;
        __syncthreads();
        sh[t] += u;
        __syncthreads();
    }
    // lookback by warp 0 (all 98 blocks co-resident: <=148 SMs, no deadlock)
    if (b == 0) {
        if (t == 0) s_prefix = 0;
    } else if (t < 32) {
        int running = 0;
        int look = b - 1;
        while (true) {
            int my = look - t;
            int st = 2; unsigned val = 0;
            if (my >= 0) {
                unsigned long long vv;
                do { vv = *(volatile unsigned long long*)&d_lb[my]; }
                while ((vv >> 32) == 0);
                st = (int)(vv >> 32);
                val = (unsigned)vv;
            }
            unsigned ball = __ballot_sync(~0u, st == 2);
            if (ball) {
                int fl = __ffs(ball) - 1;
                int contrib = (t <= fl) ? (int)val : 0;
#pragma unroll
                for (int o = 16; o; o >>= 1) contrib += __shfl_down_sync(~0u, contrib, o);
                if (t == 0) {
                    s_prefix = running + contrib;
                    atomicExch(&d_lb[b], LB_PRE | (unsigned)(s_prefix + s_total));
                }
                break;
            } else {
                int contrib = (int)val;
#pragma unroll
                for (int o = 16; o; o >>= 1) contrib += __shfl_down_sync(~0u, contrib, o);
                running += __shfl_sync(~0u, contrib, 0);
                look -= 32;
            }
        }
    }
    __syncthreads();
    d_rowstart[i] = s_prefix + sh[t] - c;
    if (b == NBLK - 1 && t == 1023) d_rowstart[NPAD] = s_prefix + sh[1023];
}

// backward fill: drains d_cnt back to 0 (keeps the zero-on-entry invariant)
__global__ void k_fill(const int* __restrict__ ei, int E, int N) {
    int e = blockIdx.x * blockDim.x + threadIdx.x;
    if (e < E) {
        int s = ei[e];
        unsigned d = (unsigned)ei[E + e];
        if (d < (unsigned)N) {
            int pos = d_rowstart[d] + atomicSub(&d_cnt[d], 1) - 1;
            d_csr[pos] = s;
        }
    }
}

// ---------------- GEMM1: h1 = x(Nx128) @ W1(128x64) -> d_gh fp16 (raw) ----------------
__global__ __launch_bounds__(256)
void k_gemm1(const float* __restrict__ A, const float* __restrict__ W, int N) {
    constexpr int K   = 128;
    constexpr int KC  = 64;
    constexpr int AST = 72;
    constexpr int BST = 72;
    constexpr int CST = 68;
    constexpr int SZ_AB = (128 * AST + 64 * BST) * 2;
    constexpr int SZ_C  = 128 * CST * 4;
    __shared__ __align__(16) char sm[SZ_C > SZ_AB ? SZ_C : SZ_AB];

    __half* As = (__half*)sm;
    __half* Ws = (__half*)(sm + 128 * AST * 2);
    float*  Cs = (float*)sm;

    const int t = threadIdx.x;
    const int w = t >> 5;
    const int rowBase = blockIdx.x * 128;

    wmma::fragment<wmma::accumulator, 16, 16, 16, float> acc[4];
#pragma unroll
    for (int j = 0; j < 4; j++) wmma::fill_fragment(acc[j], 0.0f);

    for (int kc = 0; kc < K; kc += KC) {
        __syncthreads();
#pragma unroll
        for (int i = 0; i < 8; i++) {
            int lin = i * 256 + t;
            int r = lin >> 4, f4 = lin & 15;
            int row = rowBase + r;
            float4 v = make_float4(0.f, 0.f, 0.f, 0.f);
            if (row < N) v = *(const float4*)&A[(size_t)row * K + kc + f4 * 4];
            *(__half2*)&As[r * AST + f4 * 4]     = __floats2half2_rn(v.x, v.y);
            *(__half2*)&As[r * AST + f4 * 4 + 2] = __floats2half2_rn(v.z, v.w);
        }
#pragma unroll
        for (int i = 0; i < 4; i++) {
            int lin = i * 256 + t;
            int k = lin >> 4, f4 = lin & 15;
            float4 v = *(const float4*)&W[(size_t)(kc + k) * 64 + f4 * 4];
            Ws[(f4 * 4 + 0) * BST + k] = __float2half(v.x);
            Ws[(f4 * 4 + 1) * BST + k] = __float2half(v.y);
            Ws[(f4 * 4 + 2) * BST + k] = __float2half(v.z);
            Ws[(f4 * 4 + 3) * BST + k] = __float2half(v.w);
        }
        __syncthreads();

#pragma unroll
        for (int kk = 0; kk < KC; kk += 16) {
            wmma::fragment<wmma::matrix_a, 16, 16, 16, __half, wmma::row_major> af;
            wmma::load_matrix_sync(af, As + w * 16 * AST + kk, AST);
#pragma unroll
            for (int j = 0; j < 4; j++) {
                wmma::fragment<wmma::matrix_b, 16, 16, 16, __half, wmma::col_major> bf;
                wmma::load_matrix_sync(bf, Ws + j * 16 * BST + kk, BST);
                wmma::mma_sync(acc[j], af, bf, acc[j]);
            }
        }
    }

    __syncthreads();
#pragma unroll
    for (int j = 0; j < 4; j++)
        wmma::store_matrix_sync(Cs + w * 16 * CST + j * 16, acc[j], CST, wmma::mem_row_major);
    __syncthreads();

#pragma unroll
    for (int i = 0; i < 8; i++) {
        int lin = i * 256 + t;
        int r = lin >> 4, f4 = lin & 15;
        float4 v = *(const float4*)&Cs[r * CST + f4 * 4];
        __half2 h0 = __floats2half2_rn(v.x, v.y);
        __half2 h1 = __floats2half2_rn(v.z, v.w);
        uint2 u;
        u.x = *(unsigned*)&h0; u.y = *(unsigned*)&h1;
        *(uint2*)&d_gh[(size_t)(rowBase + r) * 64 + f4 * 4] = u;
    }
}

// ---------------- fused gather(layer1) + GEMM2 -> d_gh2 = (relu(agg1+b1) @ W2) * dis ----------------
__global__ __launch_bounds__(256)
void k_gg2(const float* __restrict__ W, const float* __restrict__ b1) {
    constexpr int AST = 72;
    constexpr int BST = 72;
    constexpr int CST = 68;
    constexpr int SZ_AB = (128 * AST + 64 * BST) * 2;
    constexpr int SZ_C  = 128 * CST * 4;
    __shared__ __align__(16) char sm[SZ_C > SZ_AB ? SZ_C : SZ_AB];

    __half* As = (__half*)sm;
    __half* Ws = (__half*)(sm + 128 * AST * 2);
    float*  Cs = (float*)sm;

    const int t = threadIdx.x;
    const int w = t >> 5;
    const int lane = t & 31;
    const int sub = lane >> 3;
    const int c = (lane & 7) * 8;
    const int rowBase = blockIdx.x * 128;

    float bb[8];
    {
        float4 b0 = *(const float4*)&b1[c];
        float4 b4 = *(const float4*)&b1[c + 4];
        bb[0]=b0.x; bb[1]=b0.y; bb[2]=b0.z; bb[3]=b0.w;
        bb[4]=b4.x; bb[5]=b4.y; bb[6]=b4.z; bb[7]=b4.w;
    }

#pragma unroll 1
    for (int pass = 0; pass < 4; pass++) {
        int r = pass * 32 + w * 4 + sub;
        int node = rowBase + r;
        int beg = d_rowstart[node];
        int end = d_rowstart[node + 1];
        float dn = d_dis[node];
        float acc[8];
        {
            uint4 u = *(const uint4*)&d_gh[(size_t)node * 64 + c];
            const __half2* h = (const __half2*)&u;
#pragma unroll
            for (int i = 0; i < 4; i++) {
                float2 f = __half22float2(h[i]);
                acc[i * 2] = f.x * dn; acc[i * 2 + 1] = f.y * dn;
            }
        }
        int e = beg;
        for (; e + 3 < end; e += 4) {
            int s0 = d_csr[e], s1 = d_csr[e + 1], s2 = d_csr[e + 2], s3 = d_csr[e + 3];
            float ds0 = d_dis[s0], ds1 = d_dis[s1], ds2 = d_dis[s2], ds3 = d_dis[s3];
            uint4 u0 = *(const uint4*)&d_gh[(size_t)s0 * 64 + c];
            uint4 u1 = *(const uint4*)&d_gh[(size_t)s1 * 64 + c];
            uint4 u2 = *(const uint4*)&d_gh[(size_t)s2 * 64 + c];
            uint4 u3 = *(const uint4*)&d_gh[(size_t)s3 * 64 + c];
            const __half2* h0 = (const __half2*)&u0;
            const __half2* h1 = (const __half2*)&u1;
            const __half2* h2 = (const __half2*)&u2;
            const __half2* h3 = (const __half2*)&u3;
#pragma unroll
            for (int i = 0; i < 4; i++) {
                float2 f0 = __half22float2(h0[i]);
                float2 f1 = __half22float2(h1[i]);
                float2 f2 = __half22float2(h2[i]);
                float2 f3 = __half22float2(h3[i]);
                acc[i * 2]     += f0.x * ds0 + f1.x * ds1 + f2.x * ds2 + f3.x * ds3;
                acc[i * 2 + 1] += f0.y * ds0 + f1.y * ds1 + f2.y * ds2 + f3.y * ds3;
            }
        }
        for (; e < end; e++) {
            int s0 = d_csr[e];
            float ds0 = d_dis[s0];
            uint4 u0 = *(const uint4*)&d_gh[(size_t)s0 * 64 + c];
            const __half2* h0 = (const __half2*)&u0;
#pragma unroll
            for (int i = 0; i < 4; i++) {
                float2 f0 = __half22float2(h0[i]);
                acc[i * 2]     += f0.x * ds0;
                acc[i * 2 + 1] += f0.y * ds0;
            }
        }
        __half2 hh[4];
#pragma unroll
        for (int i = 0; i < 4; i++)
            hh[i] = __floats2half2_rn(fmaxf(acc[i * 2] * dn + bb[i * 2], 0.f),
                                      fmaxf(acc[i * 2 + 1] * dn + bb[i * 2 + 1], 0.f));
        *(uint4*)&As[r * AST + c] = *(uint4*)hh;
    }

#pragma unroll
    for (int i = 0; i < 4; i++) {
        int lin = i * 256 + t;
        int k = lin >> 4, f4 = lin & 15;
        float4 v = *(const float4*)&W[(size_t)k * 64 + f4 * 4];
        Ws[(f4 * 4 + 0) * BST + k] = __float2half(v.x);
        Ws[(f4 * 4 + 1) * BST + k] = __float2half(v.y);
        Ws[(f4 * 4 + 2) * BST + k] = __float2half(v.z);
        Ws[(f4 * 4 + 3) * BST + k] = __float2half(v.w);
    }
    __syncthreads();

    wmma::fragment<wmma::accumulator, 16, 16, 16, float> acc[4];
#pragma unroll
    for (int j = 0; j < 4; j++) wmma::fill_fragment(acc[j], 0.0f);

#pragma unroll
    for (int kk = 0; kk < 64; kk += 16) {
        wmma::fragment<wmma::matrix_a, 16, 16, 16, __half, wmma::row_major> af;
        wmma::load_matrix_sync(af, As + w * 16 * AST + kk, AST);
#pragma unroll
        for (int j = 0; j < 4; j++) {
            wmma::fragment<wmma::matrix_b, 16, 16, 16, __half, wmma::col_major> bf;
            wmma::load_matrix_sync(bf, Ws + j * 16 * BST + kk, BST);
            wmma::mma_sync(acc[j], af, bf, acc[j]);
        }
    }

    __syncthreads();
#pragma unroll
    for (int j = 0; j < 4; j++)
        wmma::store_matrix_sync(Cs + w * 16 * CST + j * 16, acc[j], CST, wmma::mem_row_major);
    __syncthreads();

#pragma unroll
    for (int i = 0; i < 8; i++) {
        int lin = i * 256 + t;
        int r = lin >> 4, f4 = lin & 15;
        float dn = d_dis[rowBase + r];
        float4 v = *(const float4*)&Cs[r * CST + f4 * 4];
        __half2 h0 = __floats2half2_rn(v.x * dn, v.y * dn);
        __half2 h1 = __floats2half2_rn(v.z * dn, v.w * dn);
        uint2 u;
        u.x = *(unsigned*)&h0; u.y = *(unsigned*)&h1;
        *(uint2*)&d_gh2[(size_t)(rowBase + r) * 64 + f4 * 4] = u;
    }
}

// ---------------- fused gather(layer2) + layer3 dot; gh2 premultiplied by dis ----------------
__global__ void k_g2l3(const float* __restrict__ W3, const float* __restrict__ b2v,
                       const float* __restrict__ b3, float* __restrict__ out, int N) {
    int idx = blockIdx.x * blockDim.x + threadIdx.x;
    int node = idx >> 3;
    if (node >= N) return;
    int lane = idx & 7;
    int c = lane * 8;
    float w3[8], bb[8];
    {
        float4 a = *(const float4*)&W3[c];
        float4 b = *(const float4*)&W3[c + 4];
        w3[0]=a.x; w3[1]=a.y; w3[2]=a.z; w3[3]=a.w;
        w3[4]=b.x; w3[5]=b.y; w3[6]=b.z; w3[7]=b.w;
        float4 p = *(const float4*)&b2v[c];
        float4 q = *(const float4*)&b2v[c + 4];
        bb[0]=p.x; bb[1]=p.y; bb[2]=p.z; bb[3]=p.w;
        bb[4]=q.x; bb[5]=q.y; bb[6]=q.z; bb[7]=q.w;
    }
    int beg = d_rowstart[node];
    int end = d_rowstart[node + 1];
    float dn = d_dis[node];
    float acc[8];
    {
        uint4 u = *(const uint4*)&d_gh2[(size_t)node * 64 + c];
        const __half2* h = (const __half2*)&u;
#pragma unroll
        for (int i = 0; i < 4; i++) {
            float2 f = __half22float2(h[i]);
            acc[i * 2] = f.x; acc[i * 2 + 1] = f.y;
        }
    }
    int e = beg;
    for (; e + 3 < end; e += 4) {
        int s0 = d_csr[e], s1 = d_csr[e + 1], s2 = d_csr[e + 2], s3 = d_csr[e + 3];
        uint4 u0 = *(const uint4*)&d_gh2[(size_t)s0 * 64 + c];
        uint4 u1 = *(const uint4*)&d_gh2[(size_t)s1 * 64 + c];
        uint4 u2 = *(const uint4*)&d_gh2[(size_t)s2 * 64 + c];
        uint4 u3 = *(const uint4*)&d_gh2[(size_t)s3 * 64 + c];
        const __half2* h0 = (const __half2*)&u0;
        const __half2* h1 = (const __half2*)&u1;
        const __half2* h2 = (const __half2*)&u2;
        const __half2* h3 = (const __half2*)&u3;
#pragma unroll
        for (int i = 0; i < 4; i++) {
            float2 f0 = __half22float2(h0[i]);
            float2 f1 = __half22float2(h1[i]);
            float2 f2 = __half22float2(h2[i]);
            float2 f3 = __half22float2(h3[i]);
            acc[i * 2]     += (f0.x + f1.x) + (f2.x + f3.x);
            acc[i * 2 + 1] += (f0.y + f1.y) + (f2.y + f3.y);
        }
    }
    for (; e < end; e++) {
        int s0 = d_csr[e];
        uint4 u0 = *(const uint4*)&d_gh2[(size_t)s0 * 64 + c];
        const __half2* h0 = (const __half2*)&u0;
#pragma unroll
        for (int i = 0; i < 4; i++) {
            float2 f0 = __half22float2(h0[i]);
            acc[i * 2]     += f0.x;
            acc[i * 2 + 1] += f0.y;
        }
    }
    float s = 0.f;
#pragma unroll
    for (int i = 0; i < 8; i++)
        s += fmaxf(acc[i] * dn + bb[i], 0.f) * w3[i];
    unsigned mask = 0xFFu << (threadIdx.x & 24);
    s += __shfl_xor_sync(mask, s, 1);
    s += __shfl_xor_sync(mask, s, 2);
    s += __shfl_xor_sync(mask, s, 4);
    if (lane == 0) {
        d_g3[node] = s * dn;
        out[node]  = s * dn * dn + b3[0];
    }
}

__global__ void k_gather_out(float* __restrict__ out, int N) {
    int i = blockIdx.x * blockDim.x + threadIdx.x;
    if (i >= N) return;
    int beg = d_rowstart[i];
    int end = d_rowstart[i + 1];
    float s0 = 0.f, s1 = 0.f, s2 = 0.f, s3 = 0.f;
    int e = beg;
    for (; e + 3 < end; e += 4) {
        s0 += d_g3[d_csr[e]];
        s1 += d_g3[d_csr[e + 1]];
        s2 += d_g3[d_csr[e + 2]];
        s3 += d_g3[d_csr[e + 3]];
    }
    for (; e < end; e++) s0 += d_g3[d_csr[e]];
    out[i] += ((s0 + s1) + (s2 + s3)) * d_dis[i];
}

// ---------------- launch ----------------
extern "C" void kernel_launch(void* const* d_in, const int* in_sizes, int n_in,
                              void* d_out, int out_size) {
    const float* x  = (const float*)d_in[0];
    const int*   ei = (const int*)d_in[1];        // int32 (JAX x64 disabled)
    const float* W1 = (const float*)d_in[2];
    const float* b1 = (const float*)d_in[3];
    const float* W2 = (const float*)d_in[4];
    const float* b2 = (const float*)d_in[5];
    const float* W3 = (const float*)d_in[6];
    const float* b3 = (const float*)d_in[7];
    float* out = (float*)d_out;

    int N = in_sizes[0] / 128;
    int E = in_sizes[1] / 2;

    static cudaStream_t s2 = nullptr;
    static cudaEvent_t ev_fork = nullptr, ev_gemm = nullptr;
    if (!s2) {
        cudaStreamCreateWithFlags(&s2, cudaStreamNonBlocking);
        cudaEventCreateWithFlags(&ev_fork, cudaEventDisableTiming);
        cudaEventCreateWithFlags(&ev_gemm, cudaEventDisableTiming);
    }

    const int gblocks = NPAD / 128;

    // fork: GEMM1 (independent of graph preprocessing) on s2
    cudaEventRecord(ev_fork, 0);
    cudaStreamWaitEvent(s2, ev_fork, 0);
    k_gemm1<<<gblocks, 256, 0, s2>>>(x, W1, N);
    cudaEventRecord(ev_gemm, s2);

    // preprocessing on the main stream: CSR by dst + norms
    k_count<<<(E + 255) / 256, 256>>>(ei, E, N);
    k_scan<<<NBLK, 1024>>>();
    k_fill<<<(E + 255) / 256, 256>>>(ei, E, N);

    // join, then fused layer-1 aggregation + layer-2 transform
    cudaStreamWaitEvent(0, ev_gemm, 0);
    k_gg2<<<gblocks, 256>>>(W2, b1);

    // fused layer-2 aggregation + layer-3 transform
    k_g2l3<<<(N * 8 + 255) / 256, 256>>>(W3, b2, b3, out, N);

    // layer-3 aggregation
    k_gather_out<<<(N + 255) / 256, 256>>>(out, N);
}